// round 7
// baseline (speedup 1.0000x reference)
#include <cuda_runtime.h>
#include <cstdint>

// Problem constants
// x: [B=2, E=512, S=128, L=128] fp32 ; W: [1536, 512] ; b: [1536]
// out: [2, 512, 128, 128] fp32
#define NB 2
#define NH 8
#define DH 64
#define NS 128
#define NL 128
// scratch layout: [b][h][s][l][d], d contiguous
#define QKV_ELEMS (NB * NH * NS * NL * DH)   // 16,777,216 floats = 64MB

__device__ __align__(256) float g_q[QKV_ELEMS];
__device__ __align__(256) float g_k[QKV_ELEMS];
__device__ __align__(256) float g_v[QKV_ELEMS];
__device__ __align__(256) float g_oc[QKV_ELEMS];

// ---------- helpers ----------
__device__ __forceinline__ uint32_t tf32u(float x) {
    uint32_t r;
    asm("cvt.rna.tf32.f32 %0, %1;" : "=r"(r) : "f"(x));
    return r;
}
__device__ __forceinline__ float tf32f(float x) { return __uint_as_float(tf32u(x)); }
__device__ __forceinline__ uint32_t fu(float x) { return __float_as_uint(x); }

__device__ __forceinline__ void mma8(float (&d)[4], const uint32_t (&a)[4], const uint32_t (&b)[2]) {
    asm volatile(
        "mma.sync.aligned.m16n8k8.row.col.f32.tf32.tf32.f32 "
        "{%0,%1,%2,%3}, {%4,%5,%6,%7}, {%8,%9}, {%0,%1,%2,%3};\n"
        : "+f"(d[0]), "+f"(d[1]), "+f"(d[2]), "+f"(d[3])
        : "r"(a[0]), "r"(a[1]), "r"(a[2]), "r"(a[3]), "r"(b[0]), "r"(b[1]));
}

// =====================================================================
// K1: QKV GEMM.  C[o, p] = sum_i W[o,i] * X[b][i][p] (+bias), p = s*128+l
// Block tile: 128 (o) x 128 (p=one s row, all l). K chunks of 32.
// Epilogue: transpose via smem, scatter to g_q/g_k/g_v [b][h][s][l][d].
// =====================================================================
#define K1_SMEM (128 * 129 * 4)   // Cs dominates (As+Bs = 2*32*132 floats fits under it)

__global__ void __launch_bounds__(256, 1) k_qkv(const float* __restrict__ X,
                                                const float* __restrict__ W,
                                                const float* __restrict__ bias) {
    extern __shared__ float sm[];
    float* As = sm;               // [32][132] k-major: As[k][m]
    float* Bs = sm + 32 * 132;    // [32][132]          Bs[k][n]
    const int tid = threadIdx.x;
    const int warp = tid >> 5, lane = tid & 31;
    const int g = lane >> 2, qc = lane & 3;
    const int wm = warp >> 2, wn = warp & 3;        // 2 x 4 warp grid
    const int o0 = blockIdx.x * 128;
    const int s = blockIdx.y;
    const int b = blockIdx.z;
    const float* Xb = X + (size_t)b * 512 * 16384 + (size_t)s * 128;

    float acc[4][4][4];
#pragma unroll
    for (int i = 0; i < 4; i++)
#pragma unroll
        for (int j = 0; j < 4; j++)
#pragma unroll
            for (int k = 0; k < 4; k++) acc[i][j][k] = 0.f;

    for (int kk = 0; kk < 512; kk += 32) {
        // Load W tile [128 o x 32 k] -> As[k][m], tf32-rounded
#pragma unroll
        for (int rep = 0; rep < 4; rep++) {
            int idx = rep * 256 + tid;        // 0..1023
            int r = idx >> 3;                 // 0..127 (o)
            int kq = (idx & 7) * 4;           // 0..28
            const float4 v = *reinterpret_cast<const float4*>(W + (size_t)(o0 + r) * 512 + kk + kq);
            As[(kq + 0) * 132 + r] = tf32f(v.x);
            As[(kq + 1) * 132 + r] = tf32f(v.y);
            As[(kq + 2) * 132 + r] = tf32f(v.z);
            As[(kq + 3) * 132 + r] = tf32f(v.w);
        }
        // Load X tile [32 k x 128 n] -> Bs[k][n]
#pragma unroll
        for (int rep = 0; rep < 4; rep++) {
            int idx = rep * 256 + tid;
            int r = idx >> 5;                 // 0..31 (k)
            int c4 = (idx & 31) * 4;          // 0..124
            const float4 v = *reinterpret_cast<const float4*>(Xb + (size_t)(kk + r) * 16384 + c4);
            float4 w4 = make_float4(tf32f(v.x), tf32f(v.y), tf32f(v.z), tf32f(v.w));
            *reinterpret_cast<float4*>(&Bs[r * 132 + c4]) = w4;
        }
        __syncthreads();
#pragma unroll
        for (int k0 = 0; k0 < 32; k0 += 8) {
            uint32_t af[4][4], bf[4][2];
#pragma unroll
            for (int mt = 0; mt < 4; mt++) {
                int m = wm * 64 + mt * 16 + g;
                af[mt][0] = fu(As[(k0 + qc) * 132 + m]);
                af[mt][1] = fu(As[(k0 + qc) * 132 + m + 8]);
                af[mt][2] = fu(As[(k0 + qc + 4) * 132 + m]);
                af[mt][3] = fu(As[(k0 + qc + 4) * 132 + m + 8]);
            }
#pragma unroll
            for (int nt = 0; nt < 4; nt++) {
                int n = wn * 32 + nt * 8 + g;
                bf[nt][0] = fu(Bs[(k0 + qc) * 132 + n]);
                bf[nt][1] = fu(Bs[(k0 + qc + 4) * 132 + n]);
            }
#pragma unroll
            for (int mt = 0; mt < 4; mt++)
#pragma unroll
                for (int nt = 0; nt < 4; nt++) mma8(acc[mt][nt], af[mt], bf[nt]);
        }
        __syncthreads();
    }

    // Stage C tile [128 o][128 l] into smem for transposed scatter
    float* Cs = sm;   // [128][129]
#pragma unroll
    for (int mt = 0; mt < 4; mt++)
#pragma unroll
        for (int nt = 0; nt < 4; nt++) {
            int r = wm * 64 + mt * 16 + g;
            int n = wn * 32 + nt * 8 + 2 * qc;
            Cs[r * 129 + n] = acc[mt][nt][0];
            Cs[r * 129 + n + 1] = acc[mt][nt][1];
            Cs[(r + 8) * 129 + n] = acc[mt][nt][2];
            Cs[(r + 8) * 129 + n + 1] = acc[mt][nt][3];
        }
    __syncthreads();

    const int sel = o0 >> 9;                 // 0=q 1=k 2=v
    const int h0 = (o0 & 511) >> 6;          // tile covers heads h0, h0+1
    float* dst = (sel == 0) ? g_q : ((sel == 1) ? g_k : g_v);
    const float scale = (sel == 0) ? 0.125f : 1.0f;   // DH^-0.5
#pragma unroll
    for (int rep = 0; rep < 16; rep++) {
        int idx = rep * 256 + tid;           // 0..4095 float4s
        int d4 = (idx & 15) * 4;             // 0..60
        int l = (idx >> 4) & 127;
        int hh = idx >> 11;                  // 0..1
        int od = hh * 64 + d4;
        float4 v;
        v.x = (Cs[(od + 0) * 129 + l] + bias[o0 + od + 0]) * scale;
        v.y = (Cs[(od + 1) * 129 + l] + bias[o0 + od + 1]) * scale;
        v.z = (Cs[(od + 2) * 129 + l] + bias[o0 + od + 2]) * scale;
        v.w = (Cs[(od + 3) * 129 + l] + bias[o0 + od + 3]) * scale;
        size_t da = (((size_t)((b * 8 + h0 + hh) * 128 + s)) * 128 + l) * 64 + d4;
        *reinterpret_cast<float4*>(dst + da) = v;
    }
}

// =====================================================================
// Attention core shared structure (written out twice):
// 128 (seq) x 128 (seq) x 64 (d) attention per CTA, 8 warps.
// Warp w owns score rows 16w..16w+15.
// =====================================================================
#define ATTN_SMEM ((3 * 128 * 68 + 128 * 132) * 4)   // 172,032 B

// K2: column attention. Block = (l, h, b). Writes g_oc[b][h][s][l][d].
__global__ void __launch_bounds__(256, 1) k_colattn() {
    extern __shared__ float sm[];
    float* Qs = sm;                   // [128][68]
    float* Ks = sm + 128 * 68;
    float* Vs = sm + 2 * 128 * 68;
    float* Ps = sm + 3 * 128 * 68;    // [128][132]
    float* Os = sm;                   // overlay on Qs: [128][68]
    const int tid = threadIdx.x;
    const int warp = tid >> 5, lane = tid & 31;
    const int g = lane >> 2, qc = lane & 3;
    const int l = blockIdx.x, h = blockIdx.y, b = blockIdx.z;
    const size_t base = (size_t)((b * 8 + h) * 128) * 8192;   // + s*8192 + l*64 + d

    // Gather Q,K,V tiles [s][d] for this column l (256B rows, coalesced)
#pragma unroll
    for (int rep = 0; rep < 8; rep++) {
        int idx = rep * 256 + tid;           // 0..2047
        int s = idx >> 4;
        int d4 = (idx & 15) * 4;
        size_t ga = base + (size_t)s * 8192 + (size_t)l * 64 + d4;
        float4 q4 = *reinterpret_cast<const float4*>(g_q + ga);
        float4 k4 = *reinterpret_cast<const float4*>(g_k + ga);
        float4 v4 = *reinterpret_cast<const float4*>(g_v + ga);
        int so = s * 68 + d4;
        *reinterpret_cast<float4*>(&Qs[so]) = make_float4(tf32f(q4.x), tf32f(q4.y), tf32f(q4.z), tf32f(q4.w));
        *reinterpret_cast<float4*>(&Ks[so]) = make_float4(tf32f(k4.x), tf32f(k4.y), tf32f(k4.z), tf32f(k4.w));
        *reinterpret_cast<float4*>(&Vs[so]) = make_float4(tf32f(v4.x), tf32f(v4.y), tf32f(v4.z), tf32f(v4.w));
    }
    __syncthreads();

    // scores[s][t] = sum_d Q[s][d] * K[t][d]
    float sc[16][4];
#pragma unroll
    for (int nt = 0; nt < 16; nt++)
#pragma unroll
        for (int k = 0; k < 4; k++) sc[nt][k] = 0.f;
    const int row = warp * 16;
#pragma unroll
    for (int k0 = 0; k0 < 64; k0 += 8) {
        uint32_t a[4];
        a[0] = fu(Qs[(row + g) * 68 + k0 + qc]);
        a[1] = fu(Qs[(row + g + 8) * 68 + k0 + qc]);
        a[2] = fu(Qs[(row + g) * 68 + k0 + qc + 4]);
        a[3] = fu(Qs[(row + g + 8) * 68 + k0 + qc + 4]);
#pragma unroll
        for (int nt = 0; nt < 16; nt++) {
            uint32_t bb[2];
            bb[0] = fu(Ks[(nt * 8 + g) * 68 + k0 + qc]);
            bb[1] = fu(Ks[(nt * 8 + g) * 68 + k0 + qc + 4]);
            mma8(sc[nt], a, bb);
        }
    }
    // softmax over t (each thread: rows {row+g, row+g+8}, 32 cols each)
    float m0 = -1e30f, m1 = -1e30f;
#pragma unroll
    for (int nt = 0; nt < 16; nt++) {
        m0 = fmaxf(m0, fmaxf(sc[nt][0], sc[nt][1]));
        m1 = fmaxf(m1, fmaxf(sc[nt][2], sc[nt][3]));
    }
    m0 = fmaxf(m0, __shfl_xor_sync(0xffffffffu, m0, 1));
    m0 = fmaxf(m0, __shfl_xor_sync(0xffffffffu, m0, 2));
    m1 = fmaxf(m1, __shfl_xor_sync(0xffffffffu, m1, 1));
    m1 = fmaxf(m1, __shfl_xor_sync(0xffffffffu, m1, 2));
    const float LOG2E = 1.4426950408889634f;
    float s0 = 0.f, s1 = 0.f;
#pragma unroll
    for (int nt = 0; nt < 16; nt++) {
        sc[nt][0] = exp2f((sc[nt][0] - m0) * LOG2E); s0 += sc[nt][0];
        sc[nt][1] = exp2f((sc[nt][1] - m0) * LOG2E); s0 += sc[nt][1];
        sc[nt][2] = exp2f((sc[nt][2] - m1) * LOG2E); s1 += sc[nt][2];
        sc[nt][3] = exp2f((sc[nt][3] - m1) * LOG2E); s1 += sc[nt][3];
    }
    s0 += __shfl_xor_sync(0xffffffffu, s0, 1);
    s0 += __shfl_xor_sync(0xffffffffu, s0, 2);
    s1 += __shfl_xor_sync(0xffffffffu, s1, 1);
    s1 += __shfl_xor_sync(0xffffffffu, s1, 2);
    const float inv0 = 1.0f / s0, inv1 = 1.0f / s1;
#pragma unroll
    for (int nt = 0; nt < 16; nt++) {
        int n = nt * 8 + 2 * qc;
        Ps[(row + g) * 132 + n] = tf32f(sc[nt][0] * inv0);
        Ps[(row + g) * 132 + n + 1] = tf32f(sc[nt][1] * inv0);
        Ps[(row + g + 8) * 132 + n] = tf32f(sc[nt][2] * inv1);
        Ps[(row + g + 8) * 132 + n + 1] = tf32f(sc[nt][3] * inv1);
    }
    __syncthreads();

    // out[s][d] = P[s][t] @ V[t][d]
    float oa[8][4];
#pragma unroll
    for (int nt = 0; nt < 8; nt++)
#pragma unroll
        for (int k = 0; k < 4; k++) oa[nt][k] = 0.f;
#pragma unroll
    for (int k0 = 0; k0 < 128; k0 += 8) {
        uint32_t a[4];
        a[0] = fu(Ps[(row + g) * 132 + k0 + qc]);
        a[1] = fu(Ps[(row + g + 8) * 132 + k0 + qc]);
        a[2] = fu(Ps[(row + g) * 132 + k0 + qc + 4]);
        a[3] = fu(Ps[(row + g + 8) * 132 + k0 + qc + 4]);
#pragma unroll
        for (int nt = 0; nt < 8; nt++) {
            uint32_t bb[2];
            bb[0] = fu(Vs[(k0 + qc) * 68 + nt * 8 + g]);
            bb[1] = fu(Vs[(k0 + qc + 4) * 68 + nt * 8 + g]);
            mma8(oa[nt], a, bb);
        }
    }
    __syncthreads();
#pragma unroll
    for (int nt = 0; nt < 8; nt++) {
        int n = nt * 8 + 2 * qc;
        Os[(row + g) * 68 + n] = oa[nt][0];
        Os[(row + g) * 68 + n + 1] = oa[nt][1];
        Os[(row + g + 8) * 68 + n] = oa[nt][2];
        Os[(row + g + 8) * 68 + n + 1] = oa[nt][3];
    }
    __syncthreads();
#pragma unroll
    for (int rep = 0; rep < 8; rep++) {
        int idx = rep * 256 + tid;
        int s = idx >> 4;
        int d4 = (idx & 15) * 4;
        float4 v = *reinterpret_cast<const float4*>(&Os[s * 68 + d4]);
        *reinterpret_cast<float4*>(g_oc + base + (size_t)s * 8192 + (size_t)l * 64 + d4) = v;
    }
}

// K3: row attention + add col result + write final output [B,512,S,L].
__global__ void __launch_bounds__(256, 1) k_rowattn(float* __restrict__ out) {
    extern __shared__ float sm[];
    float* Qs = sm;
    float* Ks = sm + 128 * 68;
    float* Vs = sm + 2 * 128 * 68;
    float* Ps = sm + 3 * 128 * 68;
    float* Os = sm;                  // [128][65] overlay
    const int tid = threadIdx.x;
    const int warp = tid >> 5, lane = tid & 31;
    const int g = lane >> 2, qc = lane & 3;
    const int s = blockIdx.x, h = blockIdx.y, b = blockIdx.z;
    const size_t rbase = (size_t)((b * 8 + h) * 128) * 8192 + (size_t)s * 8192;

    // Fully contiguous 32KB loads per tensor
#pragma unroll
    for (int rep = 0; rep < 8; rep++) {
        int idx = rep * 256 + tid;
        int l = idx >> 4;
        int d4 = (idx & 15) * 4;
        size_t ga = rbase + (size_t)idx * 4;
        float4 q4 = *reinterpret_cast<const float4*>(g_q + ga);
        float4 k4 = *reinterpret_cast<const float4*>(g_k + ga);
        float4 v4 = *reinterpret_cast<const float4*>(g_v + ga);
        int so = l * 68 + d4;
        *reinterpret_cast<float4*>(&Qs[so]) = make_float4(tf32f(q4.x), tf32f(q4.y), tf32f(q4.z), tf32f(q4.w));
        *reinterpret_cast<float4*>(&Ks[so]) = make_float4(tf32f(k4.x), tf32f(k4.y), tf32f(k4.z), tf32f(k4.w));
        *reinterpret_cast<float4*>(&Vs[so]) = make_float4(tf32f(v4.x), tf32f(v4.y), tf32f(v4.z), tf32f(v4.w));
    }
    __syncthreads();

    float sc[16][4];
#pragma unroll
    for (int nt = 0; nt < 16; nt++)
#pragma unroll
        for (int k = 0; k < 4; k++) sc[nt][k] = 0.f;
    const int row = warp * 16;
#pragma unroll
    for (int k0 = 0; k0 < 64; k0 += 8) {
        uint32_t a[4];
        a[0] = fu(Qs[(row + g) * 68 + k0 + qc]);
        a[1] = fu(Qs[(row + g + 8) * 68 + k0 + qc]);
        a[2] = fu(Qs[(row + g) * 68 + k0 + qc + 4]);
        a[3] = fu(Qs[(row + g + 8) * 68 + k0 + qc + 4]);
#pragma unroll
        for (int nt = 0; nt < 16; nt++) {
            uint32_t bb[2];
            bb[0] = fu(Ks[(nt * 8 + g) * 68 + k0 + qc]);
            bb[1] = fu(Ks[(nt * 8 + g) * 68 + k0 + qc + 4]);
            mma8(sc[nt], a, bb);
        }
    }
    float m0 = -1e30f, m1 = -1e30f;
#pragma unroll
    for (int nt = 0; nt < 16; nt++) {
        m0 = fmaxf(m0, fmaxf(sc[nt][0], sc[nt][1]));
        m1 = fmaxf(m1, fmaxf(sc[nt][2], sc[nt][3]));
    }
    m0 = fmaxf(m0, __shfl_xor_sync(0xffffffffu, m0, 1));
    m0 = fmaxf(m0, __shfl_xor_sync(0xffffffffu, m0, 2));
    m1 = fmaxf(m1, __shfl_xor_sync(0xffffffffu, m1, 1));
    m1 = fmaxf(m1, __shfl_xor_sync(0xffffffffu, m1, 2));
    const float LOG2E = 1.4426950408889634f;
    float s0 = 0.f, s1 = 0.f;
#pragma unroll
    for (int nt = 0; nt < 16; nt++) {
        sc[nt][0] = exp2f((sc[nt][0] - m0) * LOG2E); s0 += sc[nt][0];
        sc[nt][1] = exp2f((sc[nt][1] - m0) * LOG2E); s0 += sc[nt][1];
        sc[nt][2] = exp2f((sc[nt][2] - m1) * LOG2E); s1 += sc[nt][2];
        sc[nt][3] = exp2f((sc[nt][3] - m1) * LOG2E); s1 += sc[nt][3];
    }
    s0 += __shfl_xor_sync(0xffffffffu, s0, 1);
    s0 += __shfl_xor_sync(0xffffffffu, s0, 2);
    s1 += __shfl_xor_sync(0xffffffffu, s1, 1);
    s1 += __shfl_xor_sync(0xffffffffu, s1, 2);
    const float inv0 = 1.0f / s0, inv1 = 1.0f / s1;
#pragma unroll
    for (int nt = 0; nt < 16; nt++) {
        int n = nt * 8 + 2 * qc;
        Ps[(row + g) * 132 + n] = tf32f(sc[nt][0] * inv0);
        Ps[(row + g) * 132 + n + 1] = tf32f(sc[nt][1] * inv0);
        Ps[(row + g + 8) * 132 + n] = tf32f(sc[nt][2] * inv1);
        Ps[(row + g + 8) * 132 + n + 1] = tf32f(sc[nt][3] * inv1);
    }
    __syncthreads();

    float oa[8][4];
#pragma unroll
    for (int nt = 0; nt < 8; nt++)
#pragma unroll
        for (int k = 0; k < 4; k++) oa[nt][k] = 0.f;
#pragma unroll
    for (int k0 = 0; k0 < 128; k0 += 8) {
        uint32_t a[4];
        a[0] = fu(Ps[(row + g) * 132 + k0 + qc]);
        a[1] = fu(Ps[(row + g + 8) * 132 + k0 + qc]);
        a[2] = fu(Ps[(row + g) * 132 + k0 + qc + 4]);
        a[3] = fu(Ps[(row + g + 8) * 132 + k0 + qc + 4]);
#pragma unroll
        for (int nt = 0; nt < 8; nt++) {
            uint32_t bb[2];
            bb[0] = fu(Vs[(k0 + qc) * 68 + nt * 8 + g]);
            bb[1] = fu(Vs[(k0 + qc + 4) * 68 + nt * 8 + g]);
            mma8(oa[nt], a, bb);
        }
    }
    __syncthreads();
    // stage row-attn out [l][d], stride 65
#pragma unroll
    for (int nt = 0; nt < 8; nt++) {
        int n = nt * 8 + 2 * qc;
        Os[(row + g) * 65 + n] = oa[nt][0];
        Os[(row + g) * 65 + n + 1] = oa[nt][1];
        Os[(row + g + 8) * 65 + n] = oa[nt][2];
        Os[(row + g + 8) * 65 + n + 1] = oa[nt][3];
    }
    __syncthreads();
    // add col-attn scratch (contiguous reads)
#pragma unroll
    for (int rep = 0; rep < 8; rep++) {
        int idx = rep * 256 + tid;
        int l = idx >> 4;
        int d4 = (idx & 15) * 4;
        float4 c4 = *reinterpret_cast<const float4*>(g_oc + rbase + (size_t)idx * 4);
        int so = l * 65 + d4;
        Os[so] += c4.x;
        Os[so + 1] += c4.y;
        Os[so + 2] += c4.z;
        Os[so + 3] += c4.w;
    }
    __syncthreads();
    // transposed, fully coalesced final write: out[b][h*64+d][s][l]
#pragma unroll
    for (int rep = 0; rep < 8; rep++) {
        int idx = rep * 256 + tid;           // 0..2047 = 64 d x 32 l4
        int d = idx >> 5;
        int l4 = (idx & 31) * 4;
        float4 v;
        v.x = Os[(l4 + 0) * 65 + d];
        v.y = Os[(l4 + 1) * 65 + d];
        v.z = Os[(l4 + 2) * 65 + d];
        v.w = Os[(l4 + 3) * 65 + d];
        size_t oaddr = (((size_t)(b * 512 + h * 64 + d)) * 128 + s) * 128 + l4;
        *reinterpret_cast<float4*>(out + oaddr) = v;
    }
}

extern "C" void kernel_launch(void* const* d_in, const int* in_sizes, int n_in,
                              void* d_out, int out_size) {
    const float* x = (const float*)d_in[0];
    const float* W = (const float*)d_in[1];
    const float* bias = (const float*)d_in[2];
    float* out = (float*)d_out;

    cudaFuncSetAttribute(k_qkv, cudaFuncAttributeMaxDynamicSharedMemorySize, K1_SMEM);
    cudaFuncSetAttribute(k_colattn, cudaFuncAttributeMaxDynamicSharedMemorySize, ATTN_SMEM);
    cudaFuncSetAttribute(k_rowattn, cudaFuncAttributeMaxDynamicSharedMemorySize, ATTN_SMEM);

    k_qkv<<<dim3(12, 128, 2), 256, K1_SMEM>>>(x, W, bias);
    k_colattn<<<dim3(128, 8, 2), 256, ATTN_SMEM>>>();
    k_rowattn<<<dim3(128, 8, 2), 256, ATTN_SMEM>>>(out);
}

// round 10
// speedup vs baseline: 1.5378x; 1.5378x over previous
#include <cuda_runtime.h>
#include <cstdint>

// Problem constants
// x: [B=2, E=512, S=128, L=128] fp32 ; W: [1536, 512] ; b: [1536]
// out: [2, 512, 128, 128] fp32
#define NB 2
#define NH 8
#define DH 64
#define NS 128
#define NL 128
#define QKV_ELEMS (NB * NH * NS * NL * DH)   // 16,777,216 floats = 64MB

__device__ __align__(256) float g_q[QKV_ELEMS];
__device__ __align__(256) float g_k[QKV_ELEMS];
__device__ __align__(256) float g_v[QKV_ELEMS];
__device__ __align__(256) float g_oc[QKV_ELEMS];

// ---------- helpers ----------
__device__ __forceinline__ uint32_t tf32u(float x) {
    uint32_t r;
    asm("cvt.rna.tf32.f32 %0, %1;" : "=r"(r) : "f"(x));
    return r;
}
__device__ __forceinline__ float tf32f(float x) { return __uint_as_float(tf32u(x)); }
__device__ __forceinline__ uint32_t fu(float x) { return __float_as_uint(x); }

__device__ __forceinline__ void mma8(float (&d)[4], const uint32_t (&a)[4], const uint32_t (&b)[2]) {
    asm volatile(
        "mma.sync.aligned.m16n8k8.row.col.f32.tf32.tf32.f32 "
        "{%0,%1,%2,%3}, {%4,%5,%6,%7}, {%8,%9}, {%0,%1,%2,%3};\n"
        : "+f"(d[0]), "+f"(d[1]), "+f"(d[2]), "+f"(d[3])
        : "r"(a[0]), "r"(a[1]), "r"(a[2]), "r"(a[3]), "r"(b[0]), "r"(b[1]));
}

__device__ __forceinline__ uint32_t smem_u32(const void* p) {
    uint32_t a;
    asm("{ .reg .u64 t; cvta.to.shared.u64 t, %1; cvt.u32.u64 %0, t; }" : "=r"(a) : "l"(p));
    return a;
}
__device__ __forceinline__ void cpa16(uint32_t dst, const void* src) {
    asm volatile("cp.async.cg.shared.global [%0], [%1], 16;" :: "r"(dst), "l"(src) : "memory");
}
#define CP_COMMIT() asm volatile("cp.async.commit_group;" ::: "memory")
#define CP_WAIT(n)  asm volatile("cp.async.wait_group %0;" :: "n"(n) : "memory")

// =====================================================================
// K1: QKV GEMM.  C[o, p] = sum_i W[o,i] * X[b][i][p] (+bias), p = s*128+l
// Block tile: 128 (o) x 128 (p = one s row, all l). K chunks of 32.
// cp.async double-buffered staging; tf32 rounding at fragment-load time.
// smem layout (bytes):
//   A0 [0, 16384)      A tile buf0: [128 m][32 k], 16B-quad XOR swizzle
//   A1 [16384, 32768)
//   B0 [32768, 50176)  B tile buf0: [32 k][136 n] floats (544 B rows)
//   B1 [50176, 67584)
// Epilogue overlays Cs [128][129] floats (66048 B < 67584).
// =====================================================================
#define K1_SMEM 67584

__global__ void __launch_bounds__(256, 2) k_qkv(const float* __restrict__ X,
                                                const float* __restrict__ W,
                                                const float* __restrict__ bias) {
    extern __shared__ float sm[];
    const uint32_t sb = smem_u32(sm);
    const int tid = threadIdx.x;
    const int warp = tid >> 5, lane = tid & 31;
    const int g = lane >> 2, qc = lane & 3;
    const int wm = warp >> 2, wn = warp & 3;        // 2 x 4 warp grid
    const int o0 = blockIdx.x * 128;
    const int s = blockIdx.y;
    const int b = blockIdx.z;
    const float* Wt = W + (size_t)o0 * 512;
    const float* Xb = X + (size_t)b * 512 * 16384 + (size_t)s * 128;

    float acc[4][4][4];
#pragma unroll
    for (int i = 0; i < 4; i++)
#pragma unroll
        for (int j = 0; j < 4; j++)
#pragma unroll
            for (int k = 0; k < 4; k++) acc[i][j][k] = 0.f;

    // stage chunk c into buffer buf via cp.async (8 x 16B per thread)
    auto stage = [&](int c, int buf) {
        // A: W tile [128 o][32 k] -> rows of 32 floats, quad-swizzled
        const float* wa = Wt + c * 32;
#pragma unroll
        for (int it = 0; it < 4; it++) {
            int idx = it * 256 + tid;          // 0..1023
            int r = idx >> 3;                  // o row 0..127
            int kq = idx & 7;                  // k quad 0..7
            uint32_t dst = sb + (uint32_t)(buf * 16384 + r * 128 + ((kq ^ (r & 7)) << 4));
            cpa16(dst, wa + (size_t)r * 512 + kq * 4);
        }
        // B: X tile [32 k][128 n] -> rows of 136 floats (544 B)
        const float* xa = Xb + (size_t)(c * 32) * 16384;
#pragma unroll
        for (int it = 0; it < 4; it++) {
            int idx = it * 256 + tid;
            int r = idx >> 5;                  // k row 0..31
            int c4 = (idx & 31) * 4;           // 0..124
            uint32_t dst = sb + (uint32_t)(32768 + buf * 17408 + r * 544 + c4 * 4);
            cpa16(dst, xa + (size_t)r * 16384 + c4);
        }
    };

    auto compute = [&](int buf) {
        const float* A = sm + buf * 4096;
        const float* B = sm + 8192 + buf * 4352;
#pragma unroll
        for (int s8 = 0; s8 < 4; s8++) {
            uint32_t af[4][4], bf[4][2];
#pragma unroll
            for (int mt = 0; mt < 4; mt++) {
                int m = wm * 64 + mt * 16 + g;
                int o1 = (((2 * s8) ^ (m & 7)) << 2) + qc;
                int o2 = (((2 * s8 + 1) ^ (m & 7)) << 2) + qc;
                af[mt][0] = tf32u(A[m * 32 + o1]);
                af[mt][1] = tf32u(A[(m + 8) * 32 + o1]);
                af[mt][2] = tf32u(A[m * 32 + o2]);
                af[mt][3] = tf32u(A[(m + 8) * 32 + o2]);
            }
#pragma unroll
            for (int nt = 0; nt < 4; nt++) {
                int n = wn * 32 + nt * 8 + g;
                bf[nt][0] = tf32u(B[(8 * s8 + qc) * 136 + n]);
                bf[nt][1] = tf32u(B[(8 * s8 + qc + 4) * 136 + n]);
            }
#pragma unroll
            for (int mt = 0; mt < 4; mt++)
#pragma unroll
                for (int nt = 0; nt < 4; nt++) mma8(acc[mt][nt], af[mt], bf[nt]);
        }
    };

    stage(0, 0);
    CP_COMMIT();
    for (int c = 0; c < 16; c++) {
        const int buf = c & 1;
        if (c < 15) {
            stage(c + 1, buf ^ 1);
            CP_COMMIT();
            CP_WAIT(1);
        } else {
            CP_WAIT(0);
        }
        __syncthreads();
        compute(buf);
        __syncthreads();
    }

    // Stage C tile [128 o][128 l] into smem for transposed scatter
    float* Cs = sm;   // [128][129]
#pragma unroll
    for (int mt = 0; mt < 4; mt++)
#pragma unroll
        for (int nt = 0; nt < 4; nt++) {
            int r = wm * 64 + mt * 16 + g;
            int n = wn * 32 + nt * 8 + 2 * qc;
            Cs[r * 129 + n] = acc[mt][nt][0];
            Cs[r * 129 + n + 1] = acc[mt][nt][1];
            Cs[(r + 8) * 129 + n] = acc[mt][nt][2];
            Cs[(r + 8) * 129 + n + 1] = acc[mt][nt][3];
        }
    __syncthreads();

    const int sel = o0 >> 9;                 // 0=q 1=k 2=v
    const int h0 = (o0 & 511) >> 6;          // tile covers heads h0, h0+1
    float* dst = (sel == 0) ? g_q : ((sel == 1) ? g_k : g_v);
    const float scale = (sel == 0) ? 0.125f : 1.0f;   // DH^-0.5
#pragma unroll
    for (int rep = 0; rep < 16; rep++) {
        int idx = rep * 256 + tid;           // 0..4095 float4s
        int d4 = (idx & 15) * 4;             // 0..60
        int l = (idx >> 4) & 127;
        int hh = idx >> 11;                  // 0..1
        int od = hh * 64 + d4;
        float4 v;
        v.x = (Cs[(od + 0) * 129 + l] + bias[o0 + od + 0]) * scale;
        v.y = (Cs[(od + 1) * 129 + l] + bias[o0 + od + 1]) * scale;
        v.z = (Cs[(od + 2) * 129 + l] + bias[o0 + od + 2]) * scale;
        v.w = (Cs[(od + 3) * 129 + l] + bias[o0 + od + 3]) * scale;
        size_t da = (((size_t)((b * 8 + h0 + hh) * 128 + s)) * 128 + l) * 64 + d4;
        *reinterpret_cast<float4*>(dst + da) = v;
    }
}

// =====================================================================
// Attention core (byte-identical to R7 passing version):
// 128 (seq) x 128 (seq) x 64 (d) attention per CTA, 8 warps.
// =====================================================================
#define ATTN_SMEM ((3 * 128 * 68 + 128 * 132) * 4)   // 172,032 B

// K2: column attention. Block = (l, h, b). Writes g_oc[b][h][s][l][d].
__global__ void __launch_bounds__(256, 1) k_colattn() {
    extern __shared__ float sm[];
    float* Qs = sm;                   // [128][68]
    float* Ks = sm + 128 * 68;
    float* Vs = sm + 2 * 128 * 68;
    float* Ps = sm + 3 * 128 * 68;    // [128][132]
    float* Os = sm;                   // overlay on Qs: [128][68]
    const int tid = threadIdx.x;
    const int warp = tid >> 5, lane = tid & 31;
    const int g = lane >> 2, qc = lane & 3;
    const int l = blockIdx.x, h = blockIdx.y, b = blockIdx.z;
    const size_t base = (size_t)((b * 8 + h) * 128) * 8192;

#pragma unroll
    for (int rep = 0; rep < 8; rep++) {
        int idx = rep * 256 + tid;
        int s = idx >> 4;
        int d4 = (idx & 15) * 4;
        size_t ga = base + (size_t)s * 8192 + (size_t)l * 64 + d4;
        float4 q4 = *reinterpret_cast<const float4*>(g_q + ga);
        float4 k4 = *reinterpret_cast<const float4*>(g_k + ga);
        float4 v4 = *reinterpret_cast<const float4*>(g_v + ga);
        int so = s * 68 + d4;
        *reinterpret_cast<float4*>(&Qs[so]) = make_float4(tf32f(q4.x), tf32f(q4.y), tf32f(q4.z), tf32f(q4.w));
        *reinterpret_cast<float4*>(&Ks[so]) = make_float4(tf32f(k4.x), tf32f(k4.y), tf32f(k4.z), tf32f(k4.w));
        *reinterpret_cast<float4*>(&Vs[so]) = make_float4(tf32f(v4.x), tf32f(v4.y), tf32f(v4.z), tf32f(v4.w));
    }
    __syncthreads();

    float sc[16][4];
#pragma unroll
    for (int nt = 0; nt < 16; nt++)
#pragma unroll
        for (int k = 0; k < 4; k++) sc[nt][k] = 0.f;
    const int row = warp * 16;
#pragma unroll
    for (int k0 = 0; k0 < 64; k0 += 8) {
        uint32_t a[4];
        a[0] = fu(Qs[(row + g) * 68 + k0 + qc]);
        a[1] = fu(Qs[(row + g + 8) * 68 + k0 + qc]);
        a[2] = fu(Qs[(row + g) * 68 + k0 + qc + 4]);
        a[3] = fu(Qs[(row + g + 8) * 68 + k0 + qc + 4]);
#pragma unroll
        for (int nt = 0; nt < 16; nt++) {
            uint32_t bb[2];
            bb[0] = fu(Ks[(nt * 8 + g) * 68 + k0 + qc]);
            bb[1] = fu(Ks[(nt * 8 + g) * 68 + k0 + qc + 4]);
            mma8(sc[nt], a, bb);
        }
    }
    float m0 = -1e30f, m1 = -1e30f;
#pragma unroll
    for (int nt = 0; nt < 16; nt++) {
        m0 = fmaxf(m0, fmaxf(sc[nt][0], sc[nt][1]));
        m1 = fmaxf(m1, fmaxf(sc[nt][2], sc[nt][3]));
    }
    m0 = fmaxf(m0, __shfl_xor_sync(0xffffffffu, m0, 1));
    m0 = fmaxf(m0, __shfl_xor_sync(0xffffffffu, m0, 2));
    m1 = fmaxf(m1, __shfl_xor_sync(0xffffffffu, m1, 1));
    m1 = fmaxf(m1, __shfl_xor_sync(0xffffffffu, m1, 2));
    const float LOG2E = 1.4426950408889634f;
    float s0 = 0.f, s1 = 0.f;
#pragma unroll
    for (int nt = 0; nt < 16; nt++) {
        sc[nt][0] = exp2f((sc[nt][0] - m0) * LOG2E); s0 += sc[nt][0];
        sc[nt][1] = exp2f((sc[nt][1] - m0) * LOG2E); s0 += sc[nt][1];
        sc[nt][2] = exp2f((sc[nt][2] - m1) * LOG2E); s1 += sc[nt][2];
        sc[nt][3] = exp2f((sc[nt][3] - m1) * LOG2E); s1 += sc[nt][3];
    }
    s0 += __shfl_xor_sync(0xffffffffu, s0, 1);
    s0 += __shfl_xor_sync(0xffffffffu, s0, 2);
    s1 += __shfl_xor_sync(0xffffffffu, s1, 1);
    s1 += __shfl_xor_sync(0xffffffffu, s1, 2);
    const float inv0 = 1.0f / s0, inv1 = 1.0f / s1;
#pragma unroll
    for (int nt = 0; nt < 16; nt++) {
        int n = nt * 8 + 2 * qc;
        Ps[(row + g) * 132 + n] = tf32f(sc[nt][0] * inv0);
        Ps[(row + g) * 132 + n + 1] = tf32f(sc[nt][1] * inv0);
        Ps[(row + g + 8) * 132 + n] = tf32f(sc[nt][2] * inv1);
        Ps[(row + g + 8) * 132 + n + 1] = tf32f(sc[nt][3] * inv1);
    }
    __syncthreads();

    float oa[8][4];
#pragma unroll
    for (int nt = 0; nt < 8; nt++)
#pragma unroll
        for (int k = 0; k < 4; k++) oa[nt][k] = 0.f;
#pragma unroll
    for (int k0 = 0; k0 < 128; k0 += 8) {
        uint32_t a[4];
        a[0] = fu(Ps[(row + g) * 132 + k0 + qc]);
        a[1] = fu(Ps[(row + g + 8) * 132 + k0 + qc]);
        a[2] = fu(Ps[(row + g) * 132 + k0 + qc + 4]);
        a[3] = fu(Ps[(row + g + 8) * 132 + k0 + qc + 4]);
#pragma unroll
        for (int nt = 0; nt < 8; nt++) {
            uint32_t bb[2];
            bb[0] = fu(Vs[(k0 + qc) * 68 + nt * 8 + g]);
            bb[1] = fu(Vs[(k0 + qc + 4) * 68 + nt * 8 + g]);
            mma8(oa[nt], a, bb);
        }
    }
    __syncthreads();
#pragma unroll
    for (int nt = 0; nt < 8; nt++) {
        int n = nt * 8 + 2 * qc;
        Os[(row + g) * 68 + n] = oa[nt][0];
        Os[(row + g) * 68 + n + 1] = oa[nt][1];
        Os[(row + g + 8) * 68 + n] = oa[nt][2];
        Os[(row + g + 8) * 68 + n + 1] = oa[nt][3];
    }
    __syncthreads();
#pragma unroll
    for (int rep = 0; rep < 8; rep++) {
        int idx = rep * 256 + tid;
        int s = idx >> 4;
        int d4 = (idx & 15) * 4;
        float4 v = *reinterpret_cast<const float4*>(&Os[s * 68 + d4]);
        *reinterpret_cast<float4*>(g_oc + base + (size_t)s * 8192 + (size_t)l * 64 + d4) = v;
    }
}

// K3: row attention + add col result + write final output [B,512,S,L].
__global__ void __launch_bounds__(256, 1) k_rowattn(float* __restrict__ out) {
    extern __shared__ float sm[];
    float* Qs = sm;
    float* Ks = sm + 128 * 68;
    float* Vs = sm + 2 * 128 * 68;
    float* Ps = sm + 3 * 128 * 68;
    float* Os = sm;                  // [128][65] overlay
    const int tid = threadIdx.x;
    const int warp = tid >> 5, lane = tid & 31;
    const int g = lane >> 2, qc = lane & 3;
    const int s = blockIdx.x, h = blockIdx.y, b = blockIdx.z;
    const size_t rbase = (size_t)((b * 8 + h) * 128) * 8192 + (size_t)s * 8192;

#pragma unroll
    for (int rep = 0; rep < 8; rep++) {
        int idx = rep * 256 + tid;
        int l = idx >> 4;
        int d4 = (idx & 15) * 4;
        size_t ga = rbase + (size_t)idx * 4;
        float4 q4 = *reinterpret_cast<const float4*>(g_q + ga);
        float4 k4 = *reinterpret_cast<const float4*>(g_k + ga);
        float4 v4 = *reinterpret_cast<const float4*>(g_v + ga);
        int so = l * 68 + d4;
        *reinterpret_cast<float4*>(&Qs[so]) = make_float4(tf32f(q4.x), tf32f(q4.y), tf32f(q4.z), tf32f(q4.w));
        *reinterpret_cast<float4*>(&Ks[so]) = make_float4(tf32f(k4.x), tf32f(k4.y), tf32f(k4.z), tf32f(k4.w));
        *reinterpret_cast<float4*>(&Vs[so]) = make_float4(tf32f(v4.x), tf32f(v4.y), tf32f(v4.z), tf32f(v4.w));
    }
    __syncthreads();

    float sc[16][4];
#pragma unroll
    for (int nt = 0; nt < 16; nt++)
#pragma unroll
        for (int k = 0; k < 4; k++) sc[nt][k] = 0.f;
    const int row = warp * 16;
#pragma unroll
    for (int k0 = 0; k0 < 64; k0 += 8) {
        uint32_t a[4];
        a[0] = fu(Qs[(row + g) * 68 + k0 + qc]);
        a[1] = fu(Qs[(row + g + 8) * 68 + k0 + qc]);
        a[2] = fu(Qs[(row + g) * 68 + k0 + qc + 4]);
        a[3] = fu(Qs[(row + g + 8) * 68 + k0 + qc + 4]);
#pragma unroll
        for (int nt = 0; nt < 16; nt++) {
            uint32_t bb[2];
            bb[0] = fu(Ks[(nt * 8 + g) * 68 + k0 + qc]);
            bb[1] = fu(Ks[(nt * 8 + g) * 68 + k0 + qc + 4]);
            mma8(sc[nt], a, bb);
        }
    }
    float m0 = -1e30f, m1 = -1e30f;
#pragma unroll
    for (int nt = 0; nt < 16; nt++) {
        m0 = fmaxf(m0, fmaxf(sc[nt][0], sc[nt][1]));
        m1 = fmaxf(m1, fmaxf(sc[nt][2], sc[nt][3]));
    }
    m0 = fmaxf(m0, __shfl_xor_sync(0xffffffffu, m0, 1));
    m0 = fmaxf(m0, __shfl_xor_sync(0xffffffffu, m0, 2));
    m1 = fmaxf(m1, __shfl_xor_sync(0xffffffffu, m1, 1));
    m1 = fmaxf(m1, __shfl_xor_sync(0xffffffffu, m1, 2));
    const float LOG2E = 1.4426950408889634f;
    float s0 = 0.f, s1 = 0.f;
#pragma unroll
    for (int nt = 0; nt < 16; nt++) {
        sc[nt][0] = exp2f((sc[nt][0] - m0) * LOG2E); s0 += sc[nt][0];
        sc[nt][1] = exp2f((sc[nt][1] - m0) * LOG2E); s0 += sc[nt][1];
        sc[nt][2] = exp2f((sc[nt][2] - m1) * LOG2E); s1 += sc[nt][2];
        sc[nt][3] = exp2f((sc[nt][3] - m1) * LOG2E); s1 += sc[nt][3];
    }
    s0 += __shfl_xor_sync(0xffffffffu, s0, 1);
    s0 += __shfl_xor_sync(0xffffffffu, s0, 2);
    s1 += __shfl_xor_sync(0xffffffffu, s1, 1);
    s1 += __shfl_xor_sync(0xffffffffu, s1, 2);
    const float inv0 = 1.0f / s0, inv1 = 1.0f / s1;
#pragma unroll
    for (int nt = 0; nt < 16; nt++) {
        int n = nt * 8 + 2 * qc;
        Ps[(row + g) * 132 + n] = tf32f(sc[nt][0] * inv0);
        Ps[(row + g) * 132 + n + 1] = tf32f(sc[nt][1] * inv0);
        Ps[(row + g + 8) * 132 + n] = tf32f(sc[nt][2] * inv1);
        Ps[(row + g + 8) * 132 + n + 1] = tf32f(sc[nt][3] * inv1);
    }
    __syncthreads();

    float oa[8][4];
#pragma unroll
    for (int nt = 0; nt < 8; nt++)
#pragma unroll
        for (int k = 0; k < 4; k++) oa[nt][k] = 0.f;
#pragma unroll
    for (int k0 = 0; k0 < 128; k0 += 8) {
        uint32_t a[4];
        a[0] = fu(Ps[(row + g) * 132 + k0 + qc]);
        a[1] = fu(Ps[(row + g + 8) * 132 + k0 + qc]);
        a[2] = fu(Ps[(row + g) * 132 + k0 + qc + 4]);
        a[3] = fu(Ps[(row + g + 8) * 132 + k0 + qc + 4]);
#pragma unroll
        for (int nt = 0; nt < 8; nt++) {
            uint32_t bb[2];
            bb[0] = fu(Vs[(k0 + qc) * 68 + nt * 8 + g]);
            bb[1] = fu(Vs[(k0 + qc + 4) * 68 + nt * 8 + g]);
            mma8(oa[nt], a, bb);
        }
    }
    __syncthreads();
#pragma unroll
    for (int nt = 0; nt < 8; nt++) {
        int n = nt * 8 + 2 * qc;
        Os[(row + g) * 65 + n] = oa[nt][0];
        Os[(row + g) * 65 + n + 1] = oa[nt][1];
        Os[(row + g + 8) * 65 + n] = oa[nt][2];
        Os[(row + g + 8) * 65 + n + 1] = oa[nt][3];
    }
    __syncthreads();
#pragma unroll
    for (int rep = 0; rep < 8; rep++) {
        int idx = rep * 256 + tid;
        int l = idx >> 4;
        int d4 = (idx & 15) * 4;
        float4 c4 = *reinterpret_cast<const float4*>(g_oc + rbase + (size_t)idx * 4);
        int so = l * 65 + d4;
        Os[so] += c4.x;
        Os[so + 1] += c4.y;
        Os[so + 2] += c4.z;
        Os[so + 3] += c4.w;
    }
    __syncthreads();
#pragma unroll
    for (int rep = 0; rep < 8; rep++) {
        int idx = rep * 256 + tid;
        int d = idx >> 5;
        int l4 = (idx & 31) * 4;
        float4 v;
        v.x = Os[(l4 + 0) * 65 + d];
        v.y = Os[(l4 + 1) * 65 + d];
        v.z = Os[(l4 + 2) * 65 + d];
        v.w = Os[(l4 + 3) * 65 + d];
        size_t oaddr = (((size_t)(b * 512 + h * 64 + d)) * 128 + s) * 128 + l4;
        *reinterpret_cast<float4*>(out + oaddr) = v;
    }
}

extern "C" void kernel_launch(void* const* d_in, const int* in_sizes, int n_in,
                              void* d_out, int out_size) {
    const float* x = (const float*)d_in[0];
    const float* W = (const float*)d_in[1];
    const float* bias = (const float*)d_in[2];
    float* out = (float*)d_out;

    cudaFuncSetAttribute(k_qkv, cudaFuncAttributeMaxDynamicSharedMemorySize, K1_SMEM);
    cudaFuncSetAttribute(k_colattn, cudaFuncAttributeMaxDynamicSharedMemorySize, ATTN_SMEM);
    cudaFuncSetAttribute(k_rowattn, cudaFuncAttributeMaxDynamicSharedMemorySize, ATTN_SMEM);

    k_qkv<<<dim3(12, 128, 2), 256, K1_SMEM>>>(x, W, bias);
    k_colattn<<<dim3(128, 8, 2), 256, ATTN_SMEM>>>();
    k_rowattn<<<dim3(128, 8, 2), 256, ATTN_SMEM>>>(out);
}

// round 11
// speedup vs baseline: 1.6945x; 1.1019x over previous
#include <cuda_runtime.h>
#include <cstdint>

// Problem constants
// x: [B=2, E=512, S=128, L=128] fp32 ; W: [1536, 512] ; b: [1536]
// out: [2, 512, 128, 128] fp32
#define NB 2
#define NH 8
#define DH 64
#define NS 128
#define NL 128
#define QKV_ELEMS (NB * NH * NS * NL * DH)   // 16,777,216 floats = 64MB

__device__ __align__(256) float g_q[QKV_ELEMS];
__device__ __align__(256) float g_k[QKV_ELEMS];
__device__ __align__(256) float g_v[QKV_ELEMS];
__device__ __align__(256) float g_oc[QKV_ELEMS];
__device__ __align__(256) float g_xr[NB * 512 * 16384];   // tf32-rounded X
__device__ __align__(256) float g_wr[1536 * 512];         // tf32-rounded W

// ---------- helpers ----------
__device__ __forceinline__ uint32_t tf32u(float x) {
    uint32_t r;
    asm("cvt.rna.tf32.f32 %0, %1;" : "=r"(r) : "f"(x));
    return r;
}
__device__ __forceinline__ float tf32f(float x) { return __uint_as_float(tf32u(x)); }
__device__ __forceinline__ uint32_t fu(float x) { return __float_as_uint(x); }

__device__ __forceinline__ void mma8(float (&d)[4], const uint32_t (&a)[4], const uint32_t (&b)[2]) {
    asm volatile(
        "mma.sync.aligned.m16n8k8.row.col.f32.tf32.tf32.f32 "
        "{%0,%1,%2,%3}, {%4,%5,%6,%7}, {%8,%9}, {%0,%1,%2,%3};\n"
        : "+f"(d[0]), "+f"(d[1]), "+f"(d[2]), "+f"(d[3])
        : "r"(a[0]), "r"(a[1]), "r"(a[2]), "r"(a[3]), "r"(b[0]), "r"(b[1]));
}

__device__ __forceinline__ uint32_t smem_u32(const void* p) {
    uint32_t a;
    asm("{ .reg .u64 t; cvta.to.shared.u64 t, %1; cvt.u32.u64 %0, t; }" : "=r"(a) : "l"(p));
    return a;
}
__device__ __forceinline__ void cpa16(uint32_t dst, const void* src) {
    asm volatile("cp.async.cg.shared.global [%0], [%1], 16;" :: "r"(dst), "l"(src) : "memory");
}
#define CP_COMMIT() asm volatile("cp.async.commit_group;" ::: "memory")
#define CP_WAIT(n)  asm volatile("cp.async.wait_group %0;" :: "n"(n) : "memory")

// =====================================================================
// K0: tf32-round a buffer (grid-stride over float4s).
// =====================================================================
__global__ void k_round(const float* __restrict__ src, float* __restrict__ dst, int n4) {
    int i = blockIdx.x * blockDim.x + threadIdx.x;
    if (i < n4) {
        float4 v = reinterpret_cast<const float4*>(src)[i];
        reinterpret_cast<float4*>(dst)[i] = make_float4(tf32f(v.x), tf32f(v.y), tf32f(v.z), tf32f(v.w));
    }
}

// =====================================================================
// K1: QKV GEMM.  C[o, p] = sum_i Wr[o,i] * Xr[b][i][p] (+bias), p = s*128+l
// Operands pre-rounded to tf32 -> zero cvt in the hot loop.
// cp.async double-buffered staging.
// smem layout (bytes):
//   A0 [0, 16384)      A tile buf0: [128 m][32 k], 16B-quad XOR swizzle
//   A1 [16384, 32768)
//   B0 [32768, 50176)  B tile buf0: [32 k][136 n] floats (544 B rows)
//   B1 [50176, 67584)
// Epilogue overlays Cs [128][129] floats (66048 B < 67584).
// =====================================================================
#define K1_SMEM 67584

__global__ void __launch_bounds__(256, 2) k_qkv(const float* __restrict__ bias) {
    extern __shared__ float sm[];
    const uint32_t sb = smem_u32(sm);
    const int tid = threadIdx.x;
    const int warp = tid >> 5, lane = tid & 31;
    const int g = lane >> 2, qc = lane & 3;
    const int wm = warp >> 2, wn = warp & 3;        // 2 x 4 warp grid
    const int o0 = blockIdx.x * 128;
    const int s = blockIdx.y;
    const int b = blockIdx.z;
    const float* Wt = g_wr + (size_t)o0 * 512;
    const float* Xb = g_xr + (size_t)b * 512 * 16384 + (size_t)s * 128;

    float acc[4][4][4];
#pragma unroll
    for (int i = 0; i < 4; i++)
#pragma unroll
        for (int j = 0; j < 4; j++)
#pragma unroll
            for (int k = 0; k < 4; k++) acc[i][j][k] = 0.f;

    // stage chunk c into buffer buf via cp.async (8 x 16B per thread)
    auto stage = [&](int c, int buf) {
        const float* wa = Wt + c * 32;
#pragma unroll
        for (int it = 0; it < 4; it++) {
            int idx = it * 256 + tid;          // 0..1023
            int r = idx >> 3;                  // o row 0..127
            int kq = idx & 7;                  // k quad 0..7
            uint32_t dst = sb + (uint32_t)(buf * 16384 + r * 128 + ((kq ^ (r & 7)) << 4));
            cpa16(dst, wa + (size_t)r * 512 + kq * 4);
        }
        const float* xa = Xb + (size_t)(c * 32) * 16384;
#pragma unroll
        for (int it = 0; it < 4; it++) {
            int idx = it * 256 + tid;
            int r = idx >> 5;                  // k row 0..31
            int c4 = (idx & 31) * 4;           // 0..124
            uint32_t dst = sb + (uint32_t)(32768 + buf * 17408 + r * 544 + c4 * 4);
            cpa16(dst, xa + (size_t)r * 16384 + c4);
        }
    };

    auto compute = [&](int buf) {
        const float* A = sm + buf * 4096;
        const float* B = sm + 8192 + buf * 4352;
#pragma unroll
        for (int s8 = 0; s8 < 4; s8++) {
            uint32_t af[4][4], bf[4][2];
#pragma unroll
            for (int mt = 0; mt < 4; mt++) {
                int m = wm * 64 + mt * 16 + g;
                int o1 = (((2 * s8) ^ (m & 7)) << 2) + qc;
                int o2 = (((2 * s8 + 1) ^ (m & 7)) << 2) + qc;
                af[mt][0] = fu(A[m * 32 + o1]);
                af[mt][1] = fu(A[(m + 8) * 32 + o1]);
                af[mt][2] = fu(A[m * 32 + o2]);
                af[mt][3] = fu(A[(m + 8) * 32 + o2]);
            }
#pragma unroll
            for (int nt = 0; nt < 4; nt++) {
                int n = wn * 32 + nt * 8 + g;
                bf[nt][0] = fu(B[(8 * s8 + qc) * 136 + n]);
                bf[nt][1] = fu(B[(8 * s8 + qc + 4) * 136 + n]);
            }
#pragma unroll
            for (int mt = 0; mt < 4; mt++)
#pragma unroll
                for (int nt = 0; nt < 4; nt++) mma8(acc[mt][nt], af[mt], bf[nt]);
        }
    };

    stage(0, 0);
    CP_COMMIT();
    for (int c = 0; c < 16; c++) {
        const int buf = c & 1;
        if (c < 15) {
            stage(c + 1, buf ^ 1);
            CP_COMMIT();
            CP_WAIT(1);
        } else {
            CP_WAIT(0);
        }
        __syncthreads();
        compute(buf);
        __syncthreads();
    }

    // Stage C tile [128 o][128 l] into smem for transposed scatter
    float* Cs = sm;   // [128][129]
#pragma unroll
    for (int mt = 0; mt < 4; mt++)
#pragma unroll
        for (int nt = 0; nt < 4; nt++) {
            int r = wm * 64 + mt * 16 + g;
            int n = wn * 32 + nt * 8 + 2 * qc;
            Cs[r * 129 + n] = acc[mt][nt][0];
            Cs[r * 129 + n + 1] = acc[mt][nt][1];
            Cs[(r + 8) * 129 + n] = acc[mt][nt][2];
            Cs[(r + 8) * 129 + n + 1] = acc[mt][nt][3];
        }
    __syncthreads();

    const int sel = o0 >> 9;                 // 0=q 1=k 2=v
    const int h0 = (o0 & 511) >> 6;          // tile covers heads h0, h0+1
    float* dst = (sel == 0) ? g_q : ((sel == 1) ? g_k : g_v);
    const float scale = (sel == 0) ? 0.125f : 1.0f;   // DH^-0.5
#pragma unroll
    for (int rep = 0; rep < 16; rep++) {
        int idx = rep * 256 + tid;           // 0..4095 float4s
        int d4 = (idx & 15) * 4;             // 0..60
        int l = (idx >> 4) & 127;
        int hh = idx >> 11;                  // 0..1
        int od = hh * 64 + d4;
        float4 v;
        v.x = (Cs[(od + 0) * 129 + l] + bias[o0 + od + 0]) * scale;
        v.y = (Cs[(od + 1) * 129 + l] + bias[o0 + od + 1]) * scale;
        v.z = (Cs[(od + 2) * 129 + l] + bias[o0 + od + 2]) * scale;
        v.w = (Cs[(od + 3) * 129 + l] + bias[o0 + od + 3]) * scale;
        size_t da = (((size_t)((b * 8 + h0 + hh) * 128 + s)) * 128 + l) * 64 + d4;
        *reinterpret_cast<float4*>(dst + da) = v;
    }
}

// =====================================================================
// Attention core: 128 x 128 x 64 per CTA, 8 warps.
// smem: Qs[128][68] | Ks[128][68] | Vs[128][68] = 104,448 B total.
// Ps[128][132] OVERLAYS Qs+Ks (P written only after Q,K dead, with a
// syncthreads in between) -> 2 CTAs/SM.
// =====================================================================
#define ATTN_SMEM (3 * 128 * 68 * 4)   // 104,448 B

// K2: column attention. Block = (l, h, b). Writes g_oc[b][h][s][l][d].
__global__ void __launch_bounds__(256, 2) k_colattn() {
    extern __shared__ float sm[];
    float* Qs = sm;                   // [128][68]
    float* Ks = sm + 128 * 68;
    float* Vs = sm + 2 * 128 * 68;
    float* Ps = sm;                   // [128][132] overlay on Qs+Ks
    float* Os = sm;                   // [128][68] overlay on Ps
    const int tid = threadIdx.x;
    const int warp = tid >> 5, lane = tid & 31;
    const int g = lane >> 2, qc = lane & 3;
    const int l = blockIdx.x, h = blockIdx.y, b = blockIdx.z;
    const size_t base = (size_t)((b * 8 + h) * 128) * 8192;

#pragma unroll
    for (int rep = 0; rep < 8; rep++) {
        int idx = rep * 256 + tid;
        int s = idx >> 4;
        int d4 = (idx & 15) * 4;
        size_t ga = base + (size_t)s * 8192 + (size_t)l * 64 + d4;
        float4 q4 = *reinterpret_cast<const float4*>(g_q + ga);
        float4 k4 = *reinterpret_cast<const float4*>(g_k + ga);
        float4 v4 = *reinterpret_cast<const float4*>(g_v + ga);
        int so = s * 68 + d4;
        *reinterpret_cast<float4*>(&Qs[so]) = make_float4(tf32f(q4.x), tf32f(q4.y), tf32f(q4.z), tf32f(q4.w));
        *reinterpret_cast<float4*>(&Ks[so]) = make_float4(tf32f(k4.x), tf32f(k4.y), tf32f(k4.z), tf32f(k4.w));
        *reinterpret_cast<float4*>(&Vs[so]) = make_float4(tf32f(v4.x), tf32f(v4.y), tf32f(v4.z), tf32f(v4.w));
    }
    __syncthreads();

    float sc[16][4];
#pragma unroll
    for (int nt = 0; nt < 16; nt++)
#pragma unroll
        for (int k = 0; k < 4; k++) sc[nt][k] = 0.f;
    const int row = warp * 16;
#pragma unroll
    for (int k0 = 0; k0 < 64; k0 += 8) {
        uint32_t a[4];
        a[0] = fu(Qs[(row + g) * 68 + k0 + qc]);
        a[1] = fu(Qs[(row + g + 8) * 68 + k0 + qc]);
        a[2] = fu(Qs[(row + g) * 68 + k0 + qc + 4]);
        a[3] = fu(Qs[(row + g + 8) * 68 + k0 + qc + 4]);
#pragma unroll
        for (int nt = 0; nt < 16; nt++) {
            uint32_t bb[2];
            bb[0] = fu(Ks[(nt * 8 + g) * 68 + k0 + qc]);
            bb[1] = fu(Ks[(nt * 8 + g) * 68 + k0 + qc + 4]);
            mma8(sc[nt], a, bb);
        }
    }
    float m0 = -1e30f, m1 = -1e30f;
#pragma unroll
    for (int nt = 0; nt < 16; nt++) {
        m0 = fmaxf(m0, fmaxf(sc[nt][0], sc[nt][1]));
        m1 = fmaxf(m1, fmaxf(sc[nt][2], sc[nt][3]));
    }
    m0 = fmaxf(m0, __shfl_xor_sync(0xffffffffu, m0, 1));
    m0 = fmaxf(m0, __shfl_xor_sync(0xffffffffu, m0, 2));
    m1 = fmaxf(m1, __shfl_xor_sync(0xffffffffu, m1, 1));
    m1 = fmaxf(m1, __shfl_xor_sync(0xffffffffu, m1, 2));
    const float LOG2E = 1.4426950408889634f;
    float s0 = 0.f, s1 = 0.f;
#pragma unroll
    for (int nt = 0; nt < 16; nt++) {
        sc[nt][0] = exp2f((sc[nt][0] - m0) * LOG2E); s0 += sc[nt][0];
        sc[nt][1] = exp2f((sc[nt][1] - m0) * LOG2E); s0 += sc[nt][1];
        sc[nt][2] = exp2f((sc[nt][2] - m1) * LOG2E); s1 += sc[nt][2];
        sc[nt][3] = exp2f((sc[nt][3] - m1) * LOG2E); s1 += sc[nt][3];
    }
    s0 += __shfl_xor_sync(0xffffffffu, s0, 1);
    s0 += __shfl_xor_sync(0xffffffffu, s0, 2);
    s1 += __shfl_xor_sync(0xffffffffu, s1, 1);
    s1 += __shfl_xor_sync(0xffffffffu, s1, 2);
    const float inv0 = 1.0f / s0, inv1 = 1.0f / s1;

    // All warps finished reading Qs/Ks; Ps may now overwrite them.
    __syncthreads();
#pragma unroll
    for (int nt = 0; nt < 16; nt++) {
        int n = nt * 8 + 2 * qc;
        Ps[(row + g) * 132 + n] = tf32f(sc[nt][0] * inv0);
        Ps[(row + g) * 132 + n + 1] = tf32f(sc[nt][1] * inv0);
        Ps[(row + g + 8) * 132 + n] = tf32f(sc[nt][2] * inv1);
        Ps[(row + g + 8) * 132 + n + 1] = tf32f(sc[nt][3] * inv1);
    }
    __syncthreads();

    float oa[8][4];
#pragma unroll
    for (int nt = 0; nt < 8; nt++)
#pragma unroll
        for (int k = 0; k < 4; k++) oa[nt][k] = 0.f;
#pragma unroll
    for (int k0 = 0; k0 < 128; k0 += 8) {
        uint32_t a[4];
        a[0] = fu(Ps[(row + g) * 132 + k0 + qc]);
        a[1] = fu(Ps[(row + g + 8) * 132 + k0 + qc]);
        a[2] = fu(Ps[(row + g) * 132 + k0 + qc + 4]);
        a[3] = fu(Ps[(row + g + 8) * 132 + k0 + qc + 4]);
#pragma unroll
        for (int nt = 0; nt < 8; nt++) {
            uint32_t bb[2];
            bb[0] = fu(Vs[(k0 + qc) * 68 + nt * 8 + g]);
            bb[1] = fu(Vs[(k0 + qc + 4) * 68 + nt * 8 + g]);
            mma8(oa[nt], a, bb);
        }
    }
    __syncthreads();
#pragma unroll
    for (int nt = 0; nt < 8; nt++) {
        int n = nt * 8 + 2 * qc;
        Os[(row + g) * 68 + n] = oa[nt][0];
        Os[(row + g) * 68 + n + 1] = oa[nt][1];
        Os[(row + g + 8) * 68 + n] = oa[nt][2];
        Os[(row + g + 8) * 68 + n + 1] = oa[nt][3];
    }
    __syncthreads();
#pragma unroll
    for (int rep = 0; rep < 8; rep++) {
        int idx = rep * 256 + tid;
        int s = idx >> 4;
        int d4 = (idx & 15) * 4;
        float4 v = *reinterpret_cast<const float4*>(&Os[s * 68 + d4]);
        *reinterpret_cast<float4*>(g_oc + base + (size_t)s * 8192 + (size_t)l * 64 + d4) = v;
    }
}

// K3: row attention + add col result + write final output [B,512,S,L].
__global__ void __launch_bounds__(256, 2) k_rowattn(float* __restrict__ out) {
    extern __shared__ float sm[];
    float* Qs = sm;
    float* Ks = sm + 128 * 68;
    float* Vs = sm + 2 * 128 * 68;
    float* Ps = sm;                  // [128][132] overlay on Qs+Ks
    float* Os = sm;                  // [128][65] overlay
    const int tid = threadIdx.x;
    const int warp = tid >> 5, lane = tid & 31;
    const int g = lane >> 2, qc = lane & 3;
    const int s = blockIdx.x, h = blockIdx.y, b = blockIdx.z;
    const size_t rbase = (size_t)((b * 8 + h) * 128) * 8192 + (size_t)s * 8192;

#pragma unroll
    for (int rep = 0; rep < 8; rep++) {
        int idx = rep * 256 + tid;
        int l = idx >> 4;
        int d4 = (idx & 15) * 4;
        size_t ga = rbase + (size_t)idx * 4;
        float4 q4 = *reinterpret_cast<const float4*>(g_q + ga);
        float4 k4 = *reinterpret_cast<const float4*>(g_k + ga);
        float4 v4 = *reinterpret_cast<const float4*>(g_v + ga);
        int so = l * 68 + d4;
        *reinterpret_cast<float4*>(&Qs[so]) = make_float4(tf32f(q4.x), tf32f(q4.y), tf32f(q4.z), tf32f(q4.w));
        *reinterpret_cast<float4*>(&Ks[so]) = make_float4(tf32f(k4.x), tf32f(k4.y), tf32f(k4.z), tf32f(k4.w));
        *reinterpret_cast<float4*>(&Vs[so]) = make_float4(tf32f(v4.x), tf32f(v4.y), tf32f(v4.z), tf32f(v4.w));
    }
    __syncthreads();

    float sc[16][4];
#pragma unroll
    for (int nt = 0; nt < 16; nt++)
#pragma unroll
        for (int k = 0; k < 4; k++) sc[nt][k] = 0.f;
    const int row = warp * 16;
#pragma unroll
    for (int k0 = 0; k0 < 64; k0 += 8) {
        uint32_t a[4];
        a[0] = fu(Qs[(row + g) * 68 + k0 + qc]);
        a[1] = fu(Qs[(row + g + 8) * 68 + k0 + qc]);
        a[2] = fu(Qs[(row + g) * 68 + k0 + qc + 4]);
        a[3] = fu(Qs[(row + g + 8) * 68 + k0 + qc + 4]);
#pragma unroll
        for (int nt = 0; nt < 16; nt++) {
            uint32_t bb[2];
            bb[0] = fu(Ks[(nt * 8 + g) * 68 + k0 + qc]);
            bb[1] = fu(Ks[(nt * 8 + g) * 68 + k0 + qc + 4]);
            mma8(sc[nt], a, bb);
        }
    }
    float m0 = -1e30f, m1 = -1e30f;
#pragma unroll
    for (int nt = 0; nt < 16; nt++) {
        m0 = fmaxf(m0, fmaxf(sc[nt][0], sc[nt][1]));
        m1 = fmaxf(m1, fmaxf(sc[nt][2], sc[nt][3]));
    }
    m0 = fmaxf(m0, __shfl_xor_sync(0xffffffffu, m0, 1));
    m0 = fmaxf(m0, __shfl_xor_sync(0xffffffffu, m0, 2));
    m1 = fmaxf(m1, __shfl_xor_sync(0xffffffffu, m1, 1));
    m1 = fmaxf(m1, __shfl_xor_sync(0xffffffffu, m1, 2));
    const float LOG2E = 1.4426950408889634f;
    float s0 = 0.f, s1 = 0.f;
#pragma unroll
    for (int nt = 0; nt < 16; nt++) {
        sc[nt][0] = exp2f((sc[nt][0] - m0) * LOG2E); s0 += sc[nt][0];
        sc[nt][1] = exp2f((sc[nt][1] - m0) * LOG2E); s0 += sc[nt][1];
        sc[nt][2] = exp2f((sc[nt][2] - m1) * LOG2E); s1 += sc[nt][2];
        sc[nt][3] = exp2f((sc[nt][3] - m1) * LOG2E); s1 += sc[nt][3];
    }
    s0 += __shfl_xor_sync(0xffffffffu, s0, 1);
    s0 += __shfl_xor_sync(0xffffffffu, s0, 2);
    s1 += __shfl_xor_sync(0xffffffffu, s1, 1);
    s1 += __shfl_xor_sync(0xffffffffu, s1, 2);
    const float inv0 = 1.0f / s0, inv1 = 1.0f / s1;

    // All warps finished reading Qs/Ks; Ps may now overwrite them.
    __syncthreads();
#pragma unroll
    for (int nt = 0; nt < 16; nt++) {
        int n = nt * 8 + 2 * qc;
        Ps[(row + g) * 132 + n] = tf32f(sc[nt][0] * inv0);
        Ps[(row + g) * 132 + n + 1] = tf32f(sc[nt][1] * inv0);
        Ps[(row + g + 8) * 132 + n] = tf32f(sc[nt][2] * inv1);
        Ps[(row + g + 8) * 132 + n + 1] = tf32f(sc[nt][3] * inv1);
    }
    __syncthreads();

    float oa[8][4];
#pragma unroll
    for (int nt = 0; nt < 8; nt++)
#pragma unroll
        for (int k = 0; k < 4; k++) oa[nt][k] = 0.f;
#pragma unroll
    for (int k0 = 0; k0 < 128; k0 += 8) {
        uint32_t a[4];
        a[0] = fu(Ps[(row + g) * 132 + k0 + qc]);
        a[1] = fu(Ps[(row + g + 8) * 132 + k0 + qc]);
        a[2] = fu(Ps[(row + g) * 132 + k0 + qc + 4]);
        a[3] = fu(Ps[(row + g + 8) * 132 + k0 + qc + 4]);
#pragma unroll
        for (int nt = 0; nt < 8; nt++) {
            uint32_t bb[2];
            bb[0] = fu(Vs[(k0 + qc) * 68 + nt * 8 + g]);
            bb[1] = fu(Vs[(k0 + qc + 4) * 68 + nt * 8 + g]);
            mma8(oa[nt], a, bb);
        }
    }
    __syncthreads();
#pragma unroll
    for (int nt = 0; nt < 8; nt++) {
        int n = nt * 8 + 2 * qc;
        Os[(row + g) * 65 + n] = oa[nt][0];
        Os[(row + g) * 65 + n + 1] = oa[nt][1];
        Os[(row + g + 8) * 65 + n] = oa[nt][2];
        Os[(row + g + 8) * 65 + n + 1] = oa[nt][3];
    }
    __syncthreads();
#pragma unroll
    for (int rep = 0; rep < 8; rep++) {
        int idx = rep * 256 + tid;
        int l = idx >> 4;
        int d4 = (idx & 15) * 4;
        float4 c4 = *reinterpret_cast<const float4*>(g_oc + rbase + (size_t)idx * 4);
        int so = l * 65 + d4;
        Os[so] += c4.x;
        Os[so + 1] += c4.y;
        Os[so + 2] += c4.z;
        Os[so + 3] += c4.w;
    }
    __syncthreads();
#pragma unroll
    for (int rep = 0; rep < 8; rep++) {
        int idx = rep * 256 + tid;
        int d = idx >> 5;
        int l4 = (idx & 31) * 4;
        float4 v;
        v.x = Os[(l4 + 0) * 65 + d];
        v.y = Os[(l4 + 1) * 65 + d];
        v.z = Os[(l4 + 2) * 65 + d];
        v.w = Os[(l4 + 3) * 65 + d];
        size_t oaddr = (((size_t)(b * 512 + h * 64 + d)) * 128 + s) * 128 + l4;
        *reinterpret_cast<float4*>(out + oaddr) = v;
    }
}

extern "C" void kernel_launch(void* const* d_in, const int* in_sizes, int n_in,
                              void* d_out, int out_size) {
    const float* x = (const float*)d_in[0];
    const float* W = (const float*)d_in[1];
    const float* bias = (const float*)d_in[2];
    float* out = (float*)d_out;

    cudaFuncSetAttribute(k_qkv, cudaFuncAttributeMaxDynamicSharedMemorySize, K1_SMEM);
    cudaFuncSetAttribute(k_colattn, cudaFuncAttributeMaxDynamicSharedMemorySize, ATTN_SMEM);
    cudaFuncSetAttribute(k_rowattn, cudaFuncAttributeMaxDynamicSharedMemorySize, ATTN_SMEM);

    // pre-round X and W to tf32 once
    {
        float* xr;  cudaGetSymbolAddress((void**)&xr, g_xr);
        float* wr;  cudaGetSymbolAddress((void**)&wr, g_wr);
        int nx4 = NB * 512 * 16384 / 4;      // 4,194,304
        int nw4 = 1536 * 512 / 4;            // 196,608
        k_round<<<(nx4 + 255) / 256, 256>>>(x, xr, nx4);
        k_round<<<(nw4 + 255) / 256, 256>>>(W, wr, nw4);
    }

    k_qkv<<<dim3(12, 128, 2), 256, K1_SMEM>>>(bias);
    k_colattn<<<dim3(128, 8, 2), 256, ATTN_SMEM>>>();
    k_rowattn<<<dim3(128, 8, 2), 256, ATTN_SMEM>>>(out);
}

// round 12
// speedup vs baseline: 1.8376x; 1.0845x over previous
#include <cuda_runtime.h>
#include <cstdint>

// Problem constants
// x: [B=2, E=512, S=128, L=128] fp32 ; W: [1536, 512] ; b: [1536]
// out: [2, 512, 128, 128] fp32
#define NB 2
#define NH 8
#define DH 64
#define NS 128
#define NL 128
#define QKV_ELEMS (NB * NH * NS * NL * DH)   // 16,777,216 floats = 64MB

__device__ __align__(256) float g_q[QKV_ELEMS];
__device__ __align__(256) float g_k[QKV_ELEMS];
__device__ __align__(256) float g_v[QKV_ELEMS];
__device__ __align__(256) float g_oc[QKV_ELEMS];
__device__ __align__(256) float g_xr[NB * 512 * 16384];   // tf32-rounded X
__device__ __align__(256) float g_wr[1536 * 512];         // tf32-rounded W

// ---------- helpers ----------
__device__ __forceinline__ uint32_t tf32u(float x) {
    uint32_t r;
    asm("cvt.rna.tf32.f32 %0, %1;" : "=r"(r) : "f"(x));
    return r;
}
__device__ __forceinline__ float tf32f(float x) { return __uint_as_float(tf32u(x)); }
__device__ __forceinline__ uint32_t fu(float x) { return __float_as_uint(x); }

__device__ __forceinline__ void mma8(float (&d)[4], const uint32_t (&a)[4], const uint32_t (&b)[2]) {
    asm volatile(
        "mma.sync.aligned.m16n8k8.row.col.f32.tf32.tf32.f32 "
        "{%0,%1,%2,%3}, {%4,%5,%6,%7}, {%8,%9}, {%0,%1,%2,%3};\n"
        : "+f"(d[0]), "+f"(d[1]), "+f"(d[2]), "+f"(d[3])
        : "r"(a[0]), "r"(a[1]), "r"(a[2]), "r"(a[3]), "r"(b[0]), "r"(b[1]));
}

__device__ __forceinline__ uint32_t smem_u32(const void* p) {
    uint32_t a;
    asm("{ .reg .u64 t; cvta.to.shared.u64 t, %1; cvt.u32.u64 %0, t; }" : "=r"(a) : "l"(p));
    return a;
}
__device__ __forceinline__ void cpa16(uint32_t dst, const void* src) {
    asm volatile("cp.async.cg.shared.global [%0], [%1], 16;" :: "r"(dst), "l"(src) : "memory");
}
#define CP_COMMIT() asm volatile("cp.async.commit_group;" ::: "memory")
#define CP_WAIT(n)  asm volatile("cp.async.wait_group %0;" :: "n"(n) : "memory")

// =====================================================================
// K0: tf32-round a buffer (grid-stride over float4s).
// =====================================================================
__global__ void k_round(const float* __restrict__ src, float* __restrict__ dst, int n4) {
    int i = blockIdx.x * blockDim.x + threadIdx.x;
    if (i < n4) {
        float4 v = reinterpret_cast<const float4*>(src)[i];
        reinterpret_cast<float4*>(dst)[i] = make_float4(tf32f(v.x), tf32f(v.y), tf32f(v.z), tf32f(v.w));
    }
}

// =====================================================================
// K1: QKV GEMM.  C[o, p] = sum_i Wr[o,i] * Xr[b][i][p] (+bias), p = s*128+l
// Operands pre-rounded to tf32 -> zero cvt in the hot loop.
// 3-stage cp.async rotation, ONE syncthreads per chunk.
// smem layout (bytes):
//   A0/A1/A2 [0, 49152)        [128 m][32 k] each, 16B-quad XOR swizzle
//   B0/B1/B2 [49152, 101376)   [32 k][136 n] floats (544 B rows) each
// Epilogue overlays Cs [128][129] floats (66048 B < 101376).
// Outputs q,k,v are written tf32-ROUNDED (post bias+scale).
// =====================================================================
#define K1_SMEM 101376

__global__ void __launch_bounds__(256, 2) k_qkv(const float* __restrict__ bias) {
    extern __shared__ float sm[];
    const uint32_t sb = smem_u32(sm);
    const int tid = threadIdx.x;
    const int warp = tid >> 5, lane = tid & 31;
    const int g = lane >> 2, qc = lane & 3;
    const int wm = warp >> 2, wn = warp & 3;        // 2 x 4 warp grid
    const int o0 = blockIdx.x * 128;
    const int s = blockIdx.y;
    const int b = blockIdx.z;
    const float* Wt = g_wr + (size_t)o0 * 512;
    const float* Xb = g_xr + (size_t)b * 512 * 16384 + (size_t)s * 128;

    float acc[4][4][4];
#pragma unroll
    for (int i = 0; i < 4; i++)
#pragma unroll
        for (int j = 0; j < 4; j++)
#pragma unroll
            for (int k = 0; k < 4; k++) acc[i][j][k] = 0.f;

    // stage chunk c into buffer buf via cp.async (8 x 16B per thread)
    auto stage = [&](int c, int buf) {
        const float* wa = Wt + c * 32;
#pragma unroll
        for (int it = 0; it < 4; it++) {
            int idx = it * 256 + tid;          // 0..1023
            int r = idx >> 3;                  // o row 0..127
            int kq = idx & 7;                  // k quad 0..7
            uint32_t dst = sb + (uint32_t)(buf * 16384 + r * 128 + ((kq ^ (r & 7)) << 4));
            cpa16(dst, wa + (size_t)r * 512 + kq * 4);
        }
        const float* xa = Xb + (size_t)(c * 32) * 16384;
#pragma unroll
        for (int it = 0; it < 4; it++) {
            int idx = it * 256 + tid;
            int r = idx >> 5;                  // k row 0..31
            int c4 = (idx & 31) * 4;           // 0..124
            uint32_t dst = sb + (uint32_t)(49152 + buf * 17408 + r * 544 + c4 * 4);
            cpa16(dst, xa + (size_t)r * 16384 + c4);
        }
    };

    auto compute = [&](int buf) {
        const float* A = sm + buf * 4096;
        const float* B = sm + 12288 + buf * 4352;
#pragma unroll
        for (int s8 = 0; s8 < 4; s8++) {
            uint32_t af[4][4], bf[4][2];
#pragma unroll
            for (int mt = 0; mt < 4; mt++) {
                int m = wm * 64 + mt * 16 + g;
                int o1 = (((2 * s8) ^ (m & 7)) << 2) + qc;
                int o2 = (((2 * s8 + 1) ^ (m & 7)) << 2) + qc;
                af[mt][0] = fu(A[m * 32 + o1]);
                af[mt][1] = fu(A[(m + 8) * 32 + o1]);
                af[mt][2] = fu(A[m * 32 + o2]);
                af[mt][3] = fu(A[(m + 8) * 32 + o2]);
            }
#pragma unroll
            for (int nt = 0; nt < 4; nt++) {
                int n = wn * 32 + nt * 8 + g;
                bf[nt][0] = fu(B[(8 * s8 + qc) * 136 + n]);
                bf[nt][1] = fu(B[(8 * s8 + qc + 4) * 136 + n]);
            }
#pragma unroll
            for (int mt = 0; mt < 4; mt++)
#pragma unroll
                for (int nt = 0; nt < 4; nt++) mma8(acc[mt][nt], af[mt], bf[nt]);
        }
    };

    stage(0, 0);
    CP_COMMIT();
    stage(1, 1);
    CP_COMMIT();
    for (int c = 0; c < 16; c++) {
        if (c < 15) { CP_WAIT(1); } else { CP_WAIT(0); }
        __syncthreads();                     // chunk c ready; compute(c-1) done everywhere
        compute(c % 3);
        if (c + 2 < 16) {
            stage(c + 2, (c + 2) % 3);       // overwrites buf (c-1)%3: safe after sync
            CP_COMMIT();
        }
    }
    __syncthreads();                          // all computes done before Cs overlay

    // Stage C tile [128 o][128 l] into smem for transposed scatter
    float* Cs = sm;   // [128][129]
#pragma unroll
    for (int mt = 0; mt < 4; mt++)
#pragma unroll
        for (int nt = 0; nt < 4; nt++) {
            int r = wm * 64 + mt * 16 + g;
            int n = wn * 32 + nt * 8 + 2 * qc;
            Cs[r * 129 + n] = acc[mt][nt][0];
            Cs[r * 129 + n + 1] = acc[mt][nt][1];
            Cs[(r + 8) * 129 + n] = acc[mt][nt][2];
            Cs[(r + 8) * 129 + n + 1] = acc[mt][nt][3];
        }
    __syncthreads();

    const int sel = o0 >> 9;                 // 0=q 1=k 2=v
    const int h0 = (o0 & 511) >> 6;          // tile covers heads h0, h0+1
    float* dst = (sel == 0) ? g_q : ((sel == 1) ? g_k : g_v);
    const float scale = (sel == 0) ? 0.125f : 1.0f;   // DH^-0.5
#pragma unroll
    for (int rep = 0; rep < 16; rep++) {
        int idx = rep * 256 + tid;           // 0..4095 float4s
        int d4 = (idx & 15) * 4;             // 0..60
        int l = (idx >> 4) & 127;
        int hh = idx >> 11;                  // 0..1
        int od = hh * 64 + d4;
        float4 v;                             // tf32-rounded at write (same values the
        v.x = tf32f((Cs[(od + 0) * 129 + l] + bias[o0 + od + 0]) * scale);   // attention
        v.y = tf32f((Cs[(od + 1) * 129 + l] + bias[o0 + od + 1]) * scale);   // kernels
        v.z = tf32f((Cs[(od + 2) * 129 + l] + bias[o0 + od + 2]) * scale);   // rounded to
        v.w = tf32f((Cs[(od + 3) * 129 + l] + bias[o0 + od + 3]) * scale);   // before)
        size_t da = (((size_t)((b * 8 + h0 + hh) * 128 + s)) * 128 + l) * 64 + d4;
        *reinterpret_cast<float4*>(dst + da) = v;
    }
}

// =====================================================================
// Attention core: 128 x 128 x 64 per CTA, 8 warps, 2 CTA/SM.
// q,k,v arrive PRE-ROUNDED -> loads are pure cp.async (no cvt/STS).
// smem: Qs[128][68] | Ks[128][68] | Vs[128][68] = 104,448 B.
// Ps[128][132] overlays Qs+Ks after Q,K dead.
// =====================================================================
#define ATTN_SMEM (3 * 128 * 68 * 4)   // 104,448 B

// K2: column attention. Block = (l, h, b). Writes g_oc[b][h][s][l][d].
__global__ void __launch_bounds__(256, 2) k_colattn() {
    extern __shared__ float sm[];
    const uint32_t sb = smem_u32(sm);
    float* Qs = sm;                   // [128][68]
    float* Ks = sm + 128 * 68;
    float* Vs = sm + 2 * 128 * 68;
    float* Ps = sm;                   // [128][132] overlay on Qs+Ks
    float* Os = sm;                   // [128][68] overlay on Ps
    const int tid = threadIdx.x;
    const int warp = tid >> 5, lane = tid & 31;
    const int g = lane >> 2, qc = lane & 3;
    const int l = blockIdx.x, h = blockIdx.y, b = blockIdx.z;
    const size_t base = (size_t)((b * 8 + h) * 128) * 8192;

#pragma unroll
    for (int rep = 0; rep < 8; rep++) {
        int idx = rep * 256 + tid;
        int s = idx >> 4;
        int d4 = (idx & 15) * 4;
        size_t ga = base + (size_t)s * 8192 + (size_t)l * 64 + d4;
        uint32_t so = (uint32_t)(s * 68 + d4) * 4;
        cpa16(sb + so, g_q + ga);
        cpa16(sb + 128 * 68 * 4 + so, g_k + ga);
        cpa16(sb + 2 * 128 * 68 * 4 + so, g_v + ga);
    }
    CP_COMMIT();
    CP_WAIT(0);
    __syncthreads();

    float sc[16][4];
#pragma unroll
    for (int nt = 0; nt < 16; nt++)
#pragma unroll
        for (int k = 0; k < 4; k++) sc[nt][k] = 0.f;
    const int row = warp * 16;
#pragma unroll
    for (int k0 = 0; k0 < 64; k0 += 8) {
        uint32_t a[4];
        a[0] = fu(Qs[(row + g) * 68 + k0 + qc]);
        a[1] = fu(Qs[(row + g + 8) * 68 + k0 + qc]);
        a[2] = fu(Qs[(row + g) * 68 + k0 + qc + 4]);
        a[3] = fu(Qs[(row + g + 8) * 68 + k0 + qc + 4]);
#pragma unroll
        for (int nt = 0; nt < 16; nt++) {
            uint32_t bb[2];
            bb[0] = fu(Ks[(nt * 8 + g) * 68 + k0 + qc]);
            bb[1] = fu(Ks[(nt * 8 + g) * 68 + k0 + qc + 4]);
            mma8(sc[nt], a, bb);
        }
    }
    float m0 = -1e30f, m1 = -1e30f;
#pragma unroll
    for (int nt = 0; nt < 16; nt++) {
        m0 = fmaxf(m0, fmaxf(sc[nt][0], sc[nt][1]));
        m1 = fmaxf(m1, fmaxf(sc[nt][2], sc[nt][3]));
    }
    m0 = fmaxf(m0, __shfl_xor_sync(0xffffffffu, m0, 1));
    m0 = fmaxf(m0, __shfl_xor_sync(0xffffffffu, m0, 2));
    m1 = fmaxf(m1, __shfl_xor_sync(0xffffffffu, m1, 1));
    m1 = fmaxf(m1, __shfl_xor_sync(0xffffffffu, m1, 2));
    const float LOG2E = 1.4426950408889634f;
    float s0 = 0.f, s1 = 0.f;
#pragma unroll
    for (int nt = 0; nt < 16; nt++) {
        sc[nt][0] = exp2f((sc[nt][0] - m0) * LOG2E); s0 += sc[nt][0];
        sc[nt][1] = exp2f((sc[nt][1] - m0) * LOG2E); s0 += sc[nt][1];
        sc[nt][2] = exp2f((sc[nt][2] - m1) * LOG2E); s1 += sc[nt][2];
        sc[nt][3] = exp2f((sc[nt][3] - m1) * LOG2E); s1 += sc[nt][3];
    }
    s0 += __shfl_xor_sync(0xffffffffu, s0, 1);
    s0 += __shfl_xor_sync(0xffffffffu, s0, 2);
    s1 += __shfl_xor_sync(0xffffffffu, s1, 1);
    s1 += __shfl_xor_sync(0xffffffffu, s1, 2);
    const float inv0 = 1.0f / s0, inv1 = 1.0f / s1;

    __syncthreads();                         // Qs/Ks dead; Ps may overwrite
#pragma unroll
    for (int nt = 0; nt < 16; nt++) {
        int n = nt * 8 + 2 * qc;
        Ps[(row + g) * 132 + n] = tf32f(sc[nt][0] * inv0);
        Ps[(row + g) * 132 + n + 1] = tf32f(sc[nt][1] * inv0);
        Ps[(row + g + 8) * 132 + n] = tf32f(sc[nt][2] * inv1);
        Ps[(row + g + 8) * 132 + n + 1] = tf32f(sc[nt][3] * inv1);
    }
    __syncthreads();

    float oa[8][4];
#pragma unroll
    for (int nt = 0; nt < 8; nt++)
#pragma unroll
        for (int k = 0; k < 4; k++) oa[nt][k] = 0.f;
#pragma unroll
    for (int k0 = 0; k0 < 128; k0 += 8) {
        uint32_t a[4];
        a[0] = fu(Ps[(row + g) * 132 + k0 + qc]);
        a[1] = fu(Ps[(row + g + 8) * 132 + k0 + qc]);
        a[2] = fu(Ps[(row + g) * 132 + k0 + qc + 4]);
        a[3] = fu(Ps[(row + g + 8) * 132 + k0 + qc + 4]);
#pragma unroll
        for (int nt = 0; nt < 8; nt++) {
            uint32_t bb[2];
            bb[0] = fu(Vs[(k0 + qc) * 68 + nt * 8 + g]);
            bb[1] = fu(Vs[(k0 + qc + 4) * 68 + nt * 8 + g]);
            mma8(oa[nt], a, bb);
        }
    }
    __syncthreads();
#pragma unroll
    for (int nt = 0; nt < 8; nt++) {
        int n = nt * 8 + 2 * qc;
        Os[(row + g) * 68 + n] = oa[nt][0];
        Os[(row + g) * 68 + n + 1] = oa[nt][1];
        Os[(row + g + 8) * 68 + n] = oa[nt][2];
        Os[(row + g + 8) * 68 + n + 1] = oa[nt][3];
    }
    __syncthreads();
#pragma unroll
    for (int rep = 0; rep < 8; rep++) {
        int idx = rep * 256 + tid;
        int s = idx >> 4;
        int d4 = (idx & 15) * 4;
        float4 v = *reinterpret_cast<const float4*>(&Os[s * 68 + d4]);
        *reinterpret_cast<float4*>(g_oc + base + (size_t)s * 8192 + (size_t)l * 64 + d4) = v;
    }
}

// K3: row attention + add col result + write final output [B,512,S,L].
__global__ void __launch_bounds__(256, 2) k_rowattn(float* __restrict__ out) {
    extern __shared__ float sm[];
    const uint32_t sb = smem_u32(sm);
    float* Qs = sm;
    float* Ks = sm + 128 * 68;
    float* Vs = sm + 2 * 128 * 68;
    float* Ps = sm;                  // [128][132] overlay on Qs+Ks
    float* Os = sm;                  // [128][65] overlay
    const int tid = threadIdx.x;
    const int warp = tid >> 5, lane = tid & 31;
    const int g = lane >> 2, qc = lane & 3;
    const int s = blockIdx.x, h = blockIdx.y, b = blockIdx.z;
    const size_t rbase = (size_t)((b * 8 + h) * 128) * 8192 + (size_t)s * 8192;

#pragma unroll
    for (int rep = 0; rep < 8; rep++) {
        int idx = rep * 256 + tid;
        int l = idx >> 4;
        int d4 = (idx & 15) * 4;
        size_t ga = rbase + (size_t)idx * 4;
        uint32_t so = (uint32_t)(l * 68 + d4) * 4;
        cpa16(sb + so, g_q + ga);
        cpa16(sb + 128 * 68 * 4 + so, g_k + ga);
        cpa16(sb + 2 * 128 * 68 * 4 + so, g_v + ga);
    }
    CP_COMMIT();
    CP_WAIT(0);
    __syncthreads();

    float sc[16][4];
#pragma unroll
    for (int nt = 0; nt < 16; nt++)
#pragma unroll
        for (int k = 0; k < 4; k++) sc[nt][k] = 0.f;
    const int row = warp * 16;
#pragma unroll
    for (int k0 = 0; k0 < 64; k0 += 8) {
        uint32_t a[4];
        a[0] = fu(Qs[(row + g) * 68 + k0 + qc]);
        a[1] = fu(Qs[(row + g + 8) * 68 + k0 + qc]);
        a[2] = fu(Qs[(row + g) * 68 + k0 + qc + 4]);
        a[3] = fu(Qs[(row + g + 8) * 68 + k0 + qc + 4]);
#pragma unroll
        for (int nt = 0; nt < 16; nt++) {
            uint32_t bb[2];
            bb[0] = fu(Ks[(nt * 8 + g) * 68 + k0 + qc]);
            bb[1] = fu(Ks[(nt * 8 + g) * 68 + k0 + qc + 4]);
            mma8(sc[nt], a, bb);
        }
    }
    float m0 = -1e30f, m1 = -1e30f;
#pragma unroll
    for (int nt = 0; nt < 16; nt++) {
        m0 = fmaxf(m0, fmaxf(sc[nt][0], sc[nt][1]));
        m1 = fmaxf(m1, fmaxf(sc[nt][2], sc[nt][3]));
    }
    m0 = fmaxf(m0, __shfl_xor_sync(0xffffffffu, m0, 1));
    m0 = fmaxf(m0, __shfl_xor_sync(0xffffffffu, m0, 2));
    m1 = fmaxf(m1, __shfl_xor_sync(0xffffffffu, m1, 1));
    m1 = fmaxf(m1, __shfl_xor_sync(0xffffffffu, m1, 2));
    const float LOG2E = 1.4426950408889634f;
    float s0 = 0.f, s1 = 0.f;
#pragma unroll
    for (int nt = 0; nt < 16; nt++) {
        sc[nt][0] = exp2f((sc[nt][0] - m0) * LOG2E); s0 += sc[nt][0];
        sc[nt][1] = exp2f((sc[nt][1] - m0) * LOG2E); s0 += sc[nt][1];
        sc[nt][2] = exp2f((sc[nt][2] - m1) * LOG2E); s1 += sc[nt][2];
        sc[nt][3] = exp2f((sc[nt][3] - m1) * LOG2E); s1 += sc[nt][3];
    }
    s0 += __shfl_xor_sync(0xffffffffu, s0, 1);
    s0 += __shfl_xor_sync(0xffffffffu, s0, 2);
    s1 += __shfl_xor_sync(0xffffffffu, s1, 1);
    s1 += __shfl_xor_sync(0xffffffffu, s1, 2);
    const float inv0 = 1.0f / s0, inv1 = 1.0f / s1;

    __syncthreads();                         // Qs/Ks dead; Ps may overwrite
#pragma unroll
    for (int nt = 0; nt < 16; nt++) {
        int n = nt * 8 + 2 * qc;
        Ps[(row + g) * 132 + n] = tf32f(sc[nt][0] * inv0);
        Ps[(row + g) * 132 + n + 1] = tf32f(sc[nt][1] * inv0);
        Ps[(row + g + 8) * 132 + n] = tf32f(sc[nt][2] * inv1);
        Ps[(row + g + 8) * 132 + n + 1] = tf32f(sc[nt][3] * inv1);
    }
    __syncthreads();

    float oa[8][4];
#pragma unroll
    for (int nt = 0; nt < 8; nt++)
#pragma unroll
        for (int k = 0; k < 4; k++) oa[nt][k] = 0.f;
#pragma unroll
    for (int k0 = 0; k0 < 128; k0 += 8) {
        uint32_t a[4];
        a[0] = fu(Ps[(row + g) * 132 + k0 + qc]);
        a[1] = fu(Ps[(row + g + 8) * 132 + k0 + qc]);
        a[2] = fu(Ps[(row + g) * 132 + k0 + qc + 4]);
        a[3] = fu(Ps[(row + g + 8) * 132 + k0 + qc + 4]);
#pragma unroll
        for (int nt = 0; nt < 8; nt++) {
            uint32_t bb[2];
            bb[0] = fu(Vs[(k0 + qc) * 68 + nt * 8 + g]);
            bb[1] = fu(Vs[(k0 + qc + 4) * 68 + nt * 8 + g]);
            mma8(oa[nt], a, bb);
        }
    }
    __syncthreads();
#pragma unroll
    for (int nt = 0; nt < 8; nt++) {
        int n = nt * 8 + 2 * qc;
        Os[(row + g) * 65 + n] = oa[nt][0];
        Os[(row + g) * 65 + n + 1] = oa[nt][1];
        Os[(row + g + 8) * 65 + n] = oa[nt][2];
        Os[(row + g + 8) * 65 + n + 1] = oa[nt][3];
    }
    __syncthreads();
#pragma unroll
    for (int rep = 0; rep < 8; rep++) {
        int idx = rep * 256 + tid;
        int l = idx >> 4;
        int d4 = (idx & 15) * 4;
        float4 c4 = *reinterpret_cast<const float4*>(g_oc + rbase + (size_t)idx * 4);
        int so = l * 65 + d4;
        Os[so] += c4.x;
        Os[so + 1] += c4.y;
        Os[so + 2] += c4.z;
        Os[so + 3] += c4.w;
    }
    __syncthreads();
#pragma unroll
    for (int rep = 0; rep < 8; rep++) {
        int idx = rep * 256 + tid;
        int d = idx >> 5;
        int l4 = (idx & 31) * 4;
        float4 v;
        v.x = Os[(l4 + 0) * 65 + d];
        v.y = Os[(l4 + 1) * 65 + d];
        v.z = Os[(l4 + 2) * 65 + d];
        v.w = Os[(l4 + 3) * 65 + d];
        size_t oaddr = (((size_t)(b * 512 + h * 64 + d)) * 128 + s) * 128 + l4;
        *reinterpret_cast<float4*>(out + oaddr) = v;
    }
}

extern "C" void kernel_launch(void* const* d_in, const int* in_sizes, int n_in,
                              void* d_out, int out_size) {
    const float* x = (const float*)d_in[0];
    const float* W = (const float*)d_in[1];
    const float* bias = (const float*)d_in[2];
    float* out = (float*)d_out;

    cudaFuncSetAttribute(k_qkv, cudaFuncAttributeMaxDynamicSharedMemorySize, K1_SMEM);
    cudaFuncSetAttribute(k_colattn, cudaFuncAttributeMaxDynamicSharedMemorySize, ATTN_SMEM);
    cudaFuncSetAttribute(k_rowattn, cudaFuncAttributeMaxDynamicSharedMemorySize, ATTN_SMEM);

    // pre-round X and W to tf32 once
    {
        float* xr;  cudaGetSymbolAddress((void**)&xr, g_xr);
        float* wr;  cudaGetSymbolAddress((void**)&wr, g_wr);
        int nx4 = NB * 512 * 16384 / 4;      // 4,194,304
        int nw4 = 1536 * 512 / 4;            // 196,608
        k_round<<<(nx4 + 255) / 256, 256>>>(x, xr, nx4);
        k_round<<<(nw4 + 255) / 256, 256>>>(W, wr, nw4);
    }

    k_qkv<<<dim3(12, 128, 2), 256, K1_SMEM>>>(bias);
    k_colattn<<<dim3(128, 8, 2), 256, ATTN_SMEM>>>();
    k_rowattn<<<dim3(128, 8, 2), 256, ATTN_SMEM>>>(out);
}

// round 13
// speedup vs baseline: 1.9980x; 1.0872x over previous
#include <cuda_runtime.h>
#include <cstdint>

// Problem constants
// x: [B=2, E=512, S=128, L=128] fp32 ; W: [1536, 512] ; b: [1536]
// out: [2, 512, 128, 128] fp32
#define NB 2
#define NH 8
#define DH 64
#define NS 128
#define NL 128
#define QKV_ELEMS (NB * NH * NS * NL * DH)   // 16,777,216 floats = 64MB

__device__ __align__(256) float g_q[QKV_ELEMS];
__device__ __align__(256) float g_k[QKV_ELEMS];
__device__ __align__(256) float g_v[QKV_ELEMS];
__device__ __align__(256) float g_oc[QKV_ELEMS];
__device__ __align__(256) float g_xr[NB * 16384 * 512];   // X transposed [b][p][i], tf32-rounded
__device__ __align__(256) float g_wr[1536 * 512];         // tf32-rounded W

// ---------- helpers ----------
__device__ __forceinline__ uint32_t tf32u(float x) {
    uint32_t r;
    asm("cvt.rna.tf32.f32 %0, %1;" : "=r"(r) : "f"(x));
    return r;
}
__device__ __forceinline__ float tf32f(float x) { return __uint_as_float(tf32u(x)); }
__device__ __forceinline__ uint32_t fu(float x) { return __float_as_uint(x); }

__device__ __forceinline__ void mma8(float (&d)[4], const uint32_t (&a)[4], const uint32_t (&b)[2]) {
    asm volatile(
        "mma.sync.aligned.m16n8k8.row.col.f32.tf32.tf32.f32 "
        "{%0,%1,%2,%3}, {%4,%5,%6,%7}, {%8,%9}, {%0,%1,%2,%3};\n"
        : "+f"(d[0]), "+f"(d[1]), "+f"(d[2]), "+f"(d[3])
        : "r"(a[0]), "r"(a[1]), "r"(a[2]), "r"(a[3]), "r"(b[0]), "r"(b[1]));
}

// ldmatrix x4: lanes 8i..8i+7 supply the 16B-row addresses of matrix i.
__device__ __forceinline__ void ldsm4(uint32_t (&r)[4], uint32_t addr) {
    asm volatile("ldmatrix.sync.aligned.m8n8.x4.shared.b16 {%0,%1,%2,%3}, [%4];"
        : "=r"(r[0]), "=r"(r[1]), "=r"(r[2]), "=r"(r[3]) : "r"(addr));
}

__device__ __forceinline__ uint32_t smem_u32(const void* p) {
    uint32_t a;
    asm("{ .reg .u64 t; cvta.to.shared.u64 t, %1; cvt.u32.u64 %0, t; }" : "=r"(a) : "l"(p));
    return a;
}
__device__ __forceinline__ void cpa16(uint32_t dst, const void* src) {
    asm volatile("cp.async.cg.shared.global [%0], [%1], 16;" :: "r"(dst), "l"(src) : "memory");
}
#define CP_COMMIT() asm volatile("cp.async.commit_group;" ::: "memory")
#define CP_WAIT(n)  asm volatile("cp.async.wait_group %0;" :: "n"(n) : "memory")

// =====================================================================
// K0a: transpose X [b][i][p] -> g_xr [b][p][i], tf32-rounded.
// =====================================================================
#define XT_SMEM (128 * 129 * 4)
__global__ void __launch_bounds__(256, 1) k_xt(const float* __restrict__ X) {
    extern __shared__ float sm[];
    float* t = sm;
    const int tid = threadIdx.x;
    const int p0 = blockIdx.x * 128, i0 = blockIdx.y * 128, b = blockIdx.z;
    const float* src = X + ((size_t)(b * 512 + i0)) * 16384 + p0;
#pragma unroll
    for (int it = 0; it < 16; it++) {
        int idx = it * 256 + tid;
        int i = idx >> 5, p4 = (idx & 31) * 4;
        float4 v = *reinterpret_cast<const float4*>(src + (size_t)i * 16384 + p4);
        t[i * 129 + p4 + 0] = tf32f(v.x);
        t[i * 129 + p4 + 1] = tf32f(v.y);
        t[i * 129 + p4 + 2] = tf32f(v.z);
        t[i * 129 + p4 + 3] = tf32f(v.w);
    }
    __syncthreads();
    float* dst = g_xr + ((size_t)(b * 16384 + p0)) * 512 + i0;
#pragma unroll
    for (int it = 0; it < 16; it++) {
        int idx = it * 256 + tid;
        int p = idx >> 5, i4 = (idx & 31) * 4;
        float4 v;
        v.x = t[(i4 + 0) * 129 + p];
        v.y = t[(i4 + 1) * 129 + p];
        v.z = t[(i4 + 2) * 129 + p];
        v.w = t[(i4 + 3) * 129 + p];
        *reinterpret_cast<float4*>(dst + (size_t)p * 512 + i4) = v;
    }
}

// K0b: tf32-round a buffer (for W).
__global__ void k_round(const float* __restrict__ src, float* __restrict__ dst, int n4) {
    int i = blockIdx.x * blockDim.x + threadIdx.x;
    if (i < n4) {
        float4 v = reinterpret_cast<const float4*>(src)[i];
        reinterpret_cast<float4*>(dst)[i] = make_float4(tf32f(v.x), tf32f(v.y), tf32f(v.z), tf32f(v.w));
    }
}

// =====================================================================
// K1: QKV GEMM.  C[o, p] = sum_i Wr[o,i] * Xr[b][p,i] (+bias), p = s*128+l
// Both operands k-major in smem: [row][32 k] 128B rows, quad XOR swizzle.
// All fragment loads via ldmatrix.x4. 3-stage cp.async rotation.
// smem: A0/A1/A2 [0,49152), B0/B1/B2 [49152,98304). Cs [128][129] overlays.
// Outputs q,k,v written tf32-ROUNDED (post bias+scale).
// =====================================================================
#define K1_SMEM 98304

__global__ void __launch_bounds__(256, 2) k_qkv(const float* __restrict__ bias) {
    extern __shared__ float sm[];
    const uint32_t sb = smem_u32(sm);
    const int tid = threadIdx.x;
    const int warp = tid >> 5, lane = tid & 31;
    const int g = lane >> 2, qc = lane & 3;
    const int sub = lane >> 3, rr = lane & 7;       // ldmatrix lane decomposition
    const int wm = warp >> 2, wn = warp & 3;        // 2 x 4 warp grid
    const int o0 = blockIdx.x * 128;
    const int s = blockIdx.y;
    const int b = blockIdx.z;
    const float* Wt = g_wr + (size_t)o0 * 512;
    const float* Bt = g_xr + ((size_t)b * 16384 + (size_t)s * 128) * 512;

    float acc[4][4][4];
#pragma unroll
    for (int i = 0; i < 4; i++)
#pragma unroll
        for (int j = 0; j < 4; j++)
#pragma unroll
            for (int k = 0; k < 4; k++) acc[i][j][k] = 0.f;

    // stage chunk c: A [128 o][32 k] and B [128 p][32 k], both swizzled
    auto stage = [&](int c, int buf) {
        const float* wa = Wt + c * 32;
#pragma unroll
        for (int it = 0; it < 4; it++) {
            int idx = it * 256 + tid;          // 0..1023
            int r = idx >> 3;                  // row 0..127
            int kq = idx & 7;                  // k quad 0..7
            uint32_t dst = sb + (uint32_t)(buf * 16384 + r * 128 + ((kq ^ (r & 7)) << 4));
            cpa16(dst, wa + (size_t)r * 512 + kq * 4);
        }
        const float* xa = Bt + c * 32;
#pragma unroll
        for (int it = 0; it < 4; it++) {
            int idx = it * 256 + tid;
            int r = idx >> 3;
            int kq = idx & 7;
            uint32_t dst = sb + (uint32_t)(49152 + buf * 16384 + r * 128 + ((kq ^ (r & 7)) << 4));
            cpa16(dst, xa + (size_t)r * 512 + kq * 4);
        }
    };

    auto compute = [&](int buf) {
        const uint32_t Ab = sb + (uint32_t)(buf * 16384);
        const uint32_t Bb = sb + (uint32_t)(49152 + buf * 16384);
#pragma unroll
        for (int s8 = 0; s8 < 4; s8++) {
            uint32_t af[4][4], bf[2][4];
#pragma unroll
            for (int mt = 0; mt < 4; mt++) {
                int row = wm * 64 + mt * 16 + ((sub & 1) << 3) + rr;
                int q = 2 * s8 + (sub >> 1);
                ldsm4(af[mt], Ab + (uint32_t)(row * 128 + ((q ^ (row & 7)) << 4)));
            }
#pragma unroll
            for (int np = 0; np < 2; np++) {
                int n = wn * 32 + np * 16 + ((sub >> 1) << 3) + rr;
                int q = 2 * s8 + (sub & 1);
                ldsm4(bf[np], Bb + (uint32_t)(n * 128 + ((q ^ (n & 7)) << 4)));
            }
#pragma unroll
            for (int mt = 0; mt < 4; mt++)
#pragma unroll
                for (int nt = 0; nt < 4; nt++) {
                    const uint32_t bb[2] = { bf[nt >> 1][(nt & 1) * 2], bf[nt >> 1][(nt & 1) * 2 + 1] };
                    mma8(acc[mt][nt], af[mt], bb);
                }
        }
    };

    stage(0, 0);
    CP_COMMIT();
    stage(1, 1);
    CP_COMMIT();
    for (int c = 0; c < 16; c++) {
        if (c < 15) { CP_WAIT(1); } else { CP_WAIT(0); }
        __syncthreads();
        compute(c % 3);
        if (c + 2 < 16) {
            stage(c + 2, (c + 2) % 3);
            CP_COMMIT();
        }
    }
    __syncthreads();

    float* Cs = sm;   // [128][129]
#pragma unroll
    for (int mt = 0; mt < 4; mt++)
#pragma unroll
        for (int nt = 0; nt < 4; nt++) {
            int r = wm * 64 + mt * 16 + g;
            int n = wn * 32 + nt * 8 + 2 * qc;
            Cs[r * 129 + n] = acc[mt][nt][0];
            Cs[r * 129 + n + 1] = acc[mt][nt][1];
            Cs[(r + 8) * 129 + n] = acc[mt][nt][2];
            Cs[(r + 8) * 129 + n + 1] = acc[mt][nt][3];
        }
    __syncthreads();

    const int sel = o0 >> 9;                 // 0=q 1=k 2=v
    const int h0 = (o0 & 511) >> 6;
    float* dst = (sel == 0) ? g_q : ((sel == 1) ? g_k : g_v);
    const float scale = (sel == 0) ? 0.125f : 1.0f;
#pragma unroll
    for (int rep = 0; rep < 16; rep++) {
        int idx = rep * 256 + tid;
        int d4 = (idx & 15) * 4;
        int l = (idx >> 4) & 127;
        int hh = idx >> 11;
        int od = hh * 64 + d4;
        float4 v;
        v.x = tf32f((Cs[(od + 0) * 129 + l] + bias[o0 + od + 0]) * scale);
        v.y = tf32f((Cs[(od + 1) * 129 + l] + bias[o0 + od + 1]) * scale);
        v.z = tf32f((Cs[(od + 2) * 129 + l] + bias[o0 + od + 2]) * scale);
        v.w = tf32f((Cs[(od + 3) * 129 + l] + bias[o0 + od + 3]) * scale);
        size_t da = (((size_t)((b * 8 + h0 + hh) * 128 + s)) * 128 + l) * 64 + d4;
        *reinterpret_cast<float4*>(dst + da) = v;
    }
}

// =====================================================================
// Attention core: 128 x 128 x 64 per CTA, 8 warps, 2 CTA/SM.
// QK: warp = 16 rows (shuffle softmax). A,B frags via ldmatrix.
// PV: warp grid 4m x 2n (32 rows x 32 cols). P frags via ldmatrix.
// smem: Qs[128][68] | Ks[128][68] | Vs[128][68]; Ps[128][132] overlays Qs+Ks.
// =====================================================================
#define ATTN_SMEM (3 * 128 * 68 * 4)   // 104,448 B
#define QS_OFF 0
#define KS_OFF (128 * 68 * 4)
#define VS_OFF (2 * 128 * 68 * 4)

// K2: column attention. Block = (l, h, b). Writes g_oc[b][h][s][l][d].
__global__ void __launch_bounds__(256, 2) k_colattn() {
    extern __shared__ float sm[];
    const uint32_t sb = smem_u32(sm);
    float* Vs = sm + 2 * 128 * 68;
    float* Ps = sm;                   // [128][132] overlay on Qs+Ks
    float* Os = sm;                   // [128][68] overlay on Ps
    const int tid = threadIdx.x;
    const int warp = tid >> 5, lane = tid & 31;
    const int g = lane >> 2, qc = lane & 3;
    const int sub = lane >> 3, rr = lane & 7;
    const int l = blockIdx.x, h = blockIdx.y, b = blockIdx.z;
    const size_t base = (size_t)((b * 8 + h) * 128) * 8192;

#pragma unroll
    for (int rep = 0; rep < 8; rep++) {
        int idx = rep * 256 + tid;
        int s = idx >> 4;
        int d4 = (idx & 15) * 4;
        size_t ga = base + (size_t)s * 8192 + (size_t)l * 64 + d4;
        uint32_t so = (uint32_t)(s * 68 + d4) * 4;
        cpa16(sb + QS_OFF + so, g_q + ga);
        cpa16(sb + KS_OFF + so, g_k + ga);
        cpa16(sb + VS_OFF + so, g_v + ga);
    }
    CP_COMMIT();
    CP_WAIT(0);
    __syncthreads();

    // ---- QK: scores[s][t], warp owns rows 16w..16w+15 ----
    float sc[16][4];
#pragma unroll
    for (int nt = 0; nt < 16; nt++)
#pragma unroll
        for (int k = 0; k < 4; k++) sc[nt][k] = 0.f;
    const int row = warp * 16;
#pragma unroll
    for (int k0 = 0; k0 < 64; k0 += 8) {
        uint32_t a[4];
        {
            int rq = row + ((sub & 1) << 3) + rr;
            ldsm4(a, sb + QS_OFF + (uint32_t)(rq * 68 + k0 + ((sub >> 1) << 2)) * 4);
        }
#pragma unroll
        for (int np = 0; np < 8; np++) {
            uint32_t bf[4];
            int n = np * 16 + ((sub >> 1) << 3) + rr;
            ldsm4(bf, sb + KS_OFF + (uint32_t)(n * 68 + k0 + ((sub & 1) << 2)) * 4);
            const uint32_t b0[2] = { bf[0], bf[1] };
            const uint32_t b1[2] = { bf[2], bf[3] };
            mma8(sc[np * 2], a, b0);
            mma8(sc[np * 2 + 1], a, b1);
        }
    }
    // ---- softmax over t ----
    float m0 = -1e30f, m1 = -1e30f;
#pragma unroll
    for (int nt = 0; nt < 16; nt++) {
        m0 = fmaxf(m0, fmaxf(sc[nt][0], sc[nt][1]));
        m1 = fmaxf(m1, fmaxf(sc[nt][2], sc[nt][3]));
    }
    m0 = fmaxf(m0, __shfl_xor_sync(0xffffffffu, m0, 1));
    m0 = fmaxf(m0, __shfl_xor_sync(0xffffffffu, m0, 2));
    m1 = fmaxf(m1, __shfl_xor_sync(0xffffffffu, m1, 1));
    m1 = fmaxf(m1, __shfl_xor_sync(0xffffffffu, m1, 2));
    const float LOG2E = 1.4426950408889634f;
    float s0 = 0.f, s1 = 0.f;
#pragma unroll
    for (int nt = 0; nt < 16; nt++) {
        sc[nt][0] = exp2f((sc[nt][0] - m0) * LOG2E); s0 += sc[nt][0];
        sc[nt][1] = exp2f((sc[nt][1] - m0) * LOG2E); s0 += sc[nt][1];
        sc[nt][2] = exp2f((sc[nt][2] - m1) * LOG2E); s1 += sc[nt][2];
        sc[nt][3] = exp2f((sc[nt][3] - m1) * LOG2E); s1 += sc[nt][3];
    }
    s0 += __shfl_xor_sync(0xffffffffu, s0, 1);
    s0 += __shfl_xor_sync(0xffffffffu, s0, 2);
    s1 += __shfl_xor_sync(0xffffffffu, s1, 1);
    s1 += __shfl_xor_sync(0xffffffffu, s1, 2);
    const float inv0 = 1.0f / s0, inv1 = 1.0f / s1;

    __syncthreads();                         // Qs/Ks dead; Ps may overwrite
#pragma unroll
    for (int nt = 0; nt < 16; nt++) {
        int n = nt * 8 + 2 * qc;
        Ps[(row + g) * 132 + n] = tf32f(sc[nt][0] * inv0);
        Ps[(row + g) * 132 + n + 1] = tf32f(sc[nt][1] * inv0);
        Ps[(row + g + 8) * 132 + n] = tf32f(sc[nt][2] * inv1);
        Ps[(row + g + 8) * 132 + n + 1] = tf32f(sc[nt][3] * inv1);
    }
    __syncthreads();

    // ---- PV: warp grid 4m x 2n; warp owns rows 32*wm2..+31, cols 32*wn2..+31 ----
    const int wm2 = warp >> 1, wn2 = warp & 1;
    float oa[2][4][4];
#pragma unroll
    for (int mt = 0; mt < 2; mt++)
#pragma unroll
        for (int j = 0; j < 4; j++)
#pragma unroll
            for (int k = 0; k < 4; k++) oa[mt][j][k] = 0.f;
#pragma unroll
    for (int k0 = 0; k0 < 128; k0 += 8) {
        uint32_t a[2][4];
#pragma unroll
        for (int mt = 0; mt < 2; mt++) {
            int rp = wm2 * 32 + mt * 16 + ((sub & 1) << 3) + rr;
            ldsm4(a[mt], sb + QS_OFF + (uint32_t)(rp * 132 + k0 + ((sub >> 1) << 2)) * 4);
        }
#pragma unroll
        for (int j = 0; j < 4; j++) {
            uint32_t bb[2];
            int n = (wn2 * 4 + j) * 8 + g;
            bb[0] = fu(Vs[(k0 + qc) * 68 + n]);
            bb[1] = fu(Vs[(k0 + qc + 4) * 68 + n]);
#pragma unroll
            for (int mt = 0; mt < 2; mt++) mma8(oa[mt][j], a[mt], bb);
        }
    }
    __syncthreads();
#pragma unroll
    for (int mt = 0; mt < 2; mt++)
#pragma unroll
        for (int j = 0; j < 4; j++) {
            int r2 = wm2 * 32 + mt * 16 + g;
            int n = (wn2 * 4 + j) * 8 + 2 * qc;
            Os[r2 * 68 + n] = oa[mt][j][0];
            Os[r2 * 68 + n + 1] = oa[mt][j][1];
            Os[(r2 + 8) * 68 + n] = oa[mt][j][2];
            Os[(r2 + 8) * 68 + n + 1] = oa[mt][j][3];
        }
    __syncthreads();
#pragma unroll
    for (int rep = 0; rep < 8; rep++) {
        int idx = rep * 256 + tid;
        int s = idx >> 4;
        int d4 = (idx & 15) * 4;
        float4 v = *reinterpret_cast<const float4*>(&Os[s * 68 + d4]);
        *reinterpret_cast<float4*>(g_oc + base + (size_t)s * 8192 + (size_t)l * 64 + d4) = v;
    }
}

// K3: row attention + add col result + write final output [B,512,S,L].
__global__ void __launch_bounds__(256, 2) k_rowattn(float* __restrict__ out) {
    extern __shared__ float sm[];
    const uint32_t sb = smem_u32(sm);
    float* Vs = sm + 2 * 128 * 68;
    float* Ps = sm;                  // [128][132] overlay on Qs+Ks
    float* Os = sm;                  // [128][65] overlay
    const int tid = threadIdx.x;
    const int warp = tid >> 5, lane = tid & 31;
    const int g = lane >> 2, qc = lane & 3;
    const int sub = lane >> 3, rr = lane & 7;
    const int s = blockIdx.x, h = blockIdx.y, b = blockIdx.z;
    const size_t rbase = (size_t)((b * 8 + h) * 128) * 8192 + (size_t)s * 8192;

#pragma unroll
    for (int rep = 0; rep < 8; rep++) {
        int idx = rep * 256 + tid;
        int l = idx >> 4;
        int d4 = (idx & 15) * 4;
        size_t ga = rbase + (size_t)idx * 4;
        uint32_t so = (uint32_t)(l * 68 + d4) * 4;
        cpa16(sb + QS_OFF + so, g_q + ga);
        cpa16(sb + KS_OFF + so, g_k + ga);
        cpa16(sb + VS_OFF + so, g_v + ga);
    }
    CP_COMMIT();
    CP_WAIT(0);
    __syncthreads();

    float sc[16][4];
#pragma unroll
    for (int nt = 0; nt < 16; nt++)
#pragma unroll
        for (int k = 0; k < 4; k++) sc[nt][k] = 0.f;
    const int row = warp * 16;
#pragma unroll
    for (int k0 = 0; k0 < 64; k0 += 8) {
        uint32_t a[4];
        {
            int rq = row + ((sub & 1) << 3) + rr;
            ldsm4(a, sb + QS_OFF + (uint32_t)(rq * 68 + k0 + ((sub >> 1) << 2)) * 4);
        }
#pragma unroll
        for (int np = 0; np < 8; np++) {
            uint32_t bf[4];
            int n = np * 16 + ((sub >> 1) << 3) + rr;
            ldsm4(bf, sb + KS_OFF + (uint32_t)(n * 68 + k0 + ((sub & 1) << 2)) * 4);
            const uint32_t b0[2] = { bf[0], bf[1] };
            const uint32_t b1[2] = { bf[2], bf[3] };
            mma8(sc[np * 2], a, b0);
            mma8(sc[np * 2 + 1], a, b1);
        }
    }
    float m0 = -1e30f, m1 = -1e30f;
#pragma unroll
    for (int nt = 0; nt < 16; nt++) {
        m0 = fmaxf(m0, fmaxf(sc[nt][0], sc[nt][1]));
        m1 = fmaxf(m1, fmaxf(sc[nt][2], sc[nt][3]));
    }
    m0 = fmaxf(m0, __shfl_xor_sync(0xffffffffu, m0, 1));
    m0 = fmaxf(m0, __shfl_xor_sync(0xffffffffu, m0, 2));
    m1 = fmaxf(m1, __shfl_xor_sync(0xffffffffu, m1, 1));
    m1 = fmaxf(m1, __shfl_xor_sync(0xffffffffu, m1, 2));
    const float LOG2E = 1.4426950408889634f;
    float s0 = 0.f, s1 = 0.f;
#pragma unroll
    for (int nt = 0; nt < 16; nt++) {
        sc[nt][0] = exp2f((sc[nt][0] - m0) * LOG2E); s0 += sc[nt][0];
        sc[nt][1] = exp2f((sc[nt][1] - m0) * LOG2E); s0 += sc[nt][1];
        sc[nt][2] = exp2f((sc[nt][2] - m1) * LOG2E); s1 += sc[nt][2];
        sc[nt][3] = exp2f((sc[nt][3] - m1) * LOG2E); s1 += sc[nt][3];
    }
    s0 += __shfl_xor_sync(0xffffffffu, s0, 1);
    s0 += __shfl_xor_sync(0xffffffffu, s0, 2);
    s1 += __shfl_xor_sync(0xffffffffu, s1, 1);
    s1 += __shfl_xor_sync(0xffffffffu, s1, 2);
    const float inv0 = 1.0f / s0, inv1 = 1.0f / s1;

    __syncthreads();
#pragma unroll
    for (int nt = 0; nt < 16; nt++) {
        int n = nt * 8 + 2 * qc;
        Ps[(row + g) * 132 + n] = tf32f(sc[nt][0] * inv0);
        Ps[(row + g) * 132 + n + 1] = tf32f(sc[nt][1] * inv0);
        Ps[(row + g + 8) * 132 + n] = tf32f(sc[nt][2] * inv1);
        Ps[(row + g + 8) * 132 + n + 1] = tf32f(sc[nt][3] * inv1);
    }
    __syncthreads();

    const int wm2 = warp >> 1, wn2 = warp & 1;
    float oa[2][4][4];
#pragma unroll
    for (int mt = 0; mt < 2; mt++)
#pragma unroll
        for (int j = 0; j < 4; j++)
#pragma unroll
            for (int k = 0; k < 4; k++) oa[mt][j][k] = 0.f;
#pragma unroll
    for (int k0 = 0; k0 < 128; k0 += 8) {
        uint32_t a[2][4];
#pragma unroll
        for (int mt = 0; mt < 2; mt++) {
            int rp = wm2 * 32 + mt * 16 + ((sub & 1) << 3) + rr;
            ldsm4(a[mt], sb + QS_OFF + (uint32_t)(rp * 132 + k0 + ((sub >> 1) << 2)) * 4);
        }
#pragma unroll
        for (int j = 0; j < 4; j++) {
            uint32_t bb[2];
            int n = (wn2 * 4 + j) * 8 + g;
            bb[0] = fu(Vs[(k0 + qc) * 68 + n]);
            bb[1] = fu(Vs[(k0 + qc + 4) * 68 + n]);
#pragma unroll
            for (int mt = 0; mt < 2; mt++) mma8(oa[mt][j], a[mt], bb);
        }
    }
    __syncthreads();
#pragma unroll
    for (int mt = 0; mt < 2; mt++)
#pragma unroll
        for (int j = 0; j < 4; j++) {
            int r2 = wm2 * 32 + mt * 16 + g;
            int n = (wn2 * 4 + j) * 8 + 2 * qc;
            Os[r2 * 65 + n] = oa[mt][j][0];
            Os[r2 * 65 + n + 1] = oa[mt][j][1];
            Os[(r2 + 8) * 65 + n] = oa[mt][j][2];
            Os[(r2 + 8) * 65 + n + 1] = oa[mt][j][3];
        }
    __syncthreads();
#pragma unroll
    for (int rep = 0; rep < 8; rep++) {
        int idx = rep * 256 + tid;
        int l = idx >> 4;
        int d4 = (idx & 15) * 4;
        float4 c4 = *reinterpret_cast<const float4*>(g_oc + rbase + (size_t)idx * 4);
        int so = l * 65 + d4;
        Os[so] += c4.x;
        Os[so + 1] += c4.y;
        Os[so + 2] += c4.z;
        Os[so + 3] += c4.w;
    }
    __syncthreads();
#pragma unroll
    for (int rep = 0; rep < 8; rep++) {
        int idx = rep * 256 + tid;
        int d = idx >> 5;
        int l4 = (idx & 31) * 4;
        float4 v;
        v.x = Os[(l4 + 0) * 65 + d];
        v.y = Os[(l4 + 1) * 65 + d];
        v.z = Os[(l4 + 2) * 65 + d];
        v.w = Os[(l4 + 3) * 65 + d];
        size_t oaddr = (((size_t)(b * 512 + h * 64 + d)) * 128 + s) * 128 + l4;
        *reinterpret_cast<float4*>(out + oaddr) = v;
    }
}

extern "C" void kernel_launch(void* const* d_in, const int* in_sizes, int n_in,
                              void* d_out, int out_size) {
    const float* x = (const float*)d_in[0];
    const float* W = (const float*)d_in[1];
    const float* bias = (const float*)d_in[2];
    float* out = (float*)d_out;

    cudaFuncSetAttribute(k_xt, cudaFuncAttributeMaxDynamicSharedMemorySize, XT_SMEM);
    cudaFuncSetAttribute(k_qkv, cudaFuncAttributeMaxDynamicSharedMemorySize, K1_SMEM);
    cudaFuncSetAttribute(k_colattn, cudaFuncAttributeMaxDynamicSharedMemorySize, ATTN_SMEM);
    cudaFuncSetAttribute(k_rowattn, cudaFuncAttributeMaxDynamicSharedMemorySize, ATTN_SMEM);

    // X: transpose + round; W: round
    k_xt<<<dim3(128, 4, 2), 256, XT_SMEM>>>(x);
    {
        float* wr;  cudaGetSymbolAddress((void**)&wr, g_wr);
        int nw4 = 1536 * 512 / 4;            // 196,608
        k_round<<<(nw4 + 255) / 256, 256>>>(W, wr, nw4);
    }

    k_qkv<<<dim3(12, 128, 2), 256, K1_SMEM>>>(bias);
    k_colattn<<<dim3(128, 8, 2), 256, ATTN_SMEM>>>();
    k_rowattn<<<dim3(128, 8, 2), 256, ATTN_SMEM>>>(out);
}

// round 14
// speedup vs baseline: 2.0322x; 1.0171x over previous
#include <cuda_runtime.h>
#include <cstdint>

// Problem constants
// x: [B=2, E=512, S=128, L=128] fp32 ; W: [1536, 512] ; b: [1536]
// out: [2, 512, 128, 128] fp32
#define NB 2
#define NH 8
#define DH 64
#define NS 128
#define NL 128
#define QKV_ELEMS (NB * NH * NS * NL * DH)   // 16,777,216 floats = 64MB

__device__ __align__(256) float g_q[QKV_ELEMS];
__device__ __align__(256) float g_k[QKV_ELEMS];
__device__ __align__(256) float g_v[QKV_ELEMS];
__device__ __align__(256) float g_oc[QKV_ELEMS];
__device__ __align__(256) float g_xr[NB * 16384 * 512];   // X transposed [b][p][i], tf32-rounded
__device__ __align__(256) float g_wr[1536 * 512];         // tf32-rounded W

// ---------- helpers ----------
__device__ __forceinline__ uint32_t tf32u(float x) {
    uint32_t r;
    asm("cvt.rna.tf32.f32 %0, %1;" : "=r"(r) : "f"(x));
    return r;
}
__device__ __forceinline__ float tf32f(float x) { return __uint_as_float(tf32u(x)); }
__device__ __forceinline__ uint32_t fu(float x) { return __float_as_uint(x); }

__device__ __forceinline__ void mma8(float (&d)[4], const uint32_t (&a)[4], const uint32_t (&b)[2]) {
    asm volatile(
        "mma.sync.aligned.m16n8k8.row.col.f32.tf32.tf32.f32 "
        "{%0,%1,%2,%3}, {%4,%5,%6,%7}, {%8,%9}, {%0,%1,%2,%3};\n"
        : "+f"(d[0]), "+f"(d[1]), "+f"(d[2]), "+f"(d[3])
        : "r"(a[0]), "r"(a[1]), "r"(a[2]), "r"(a[3]), "r"(b[0]), "r"(b[1]));
}

// ldmatrix x4: lanes 8i..8i+7 supply the 16B-row addresses of matrix i.
__device__ __forceinline__ void ldsm4(uint32_t (&r)[4], uint32_t addr) {
    asm volatile("ldmatrix.sync.aligned.m8n8.x4.shared.b16 {%0,%1,%2,%3}, [%4];"
        : "=r"(r[0]), "=r"(r[1]), "=r"(r[2]), "=r"(r[3]) : "r"(addr));
}

__device__ __forceinline__ uint32_t smem_u32(const void* p) {
    uint32_t a;
    asm("{ .reg .u64 t; cvta.to.shared.u64 t, %1; cvt.u32.u64 %0, t; }" : "=r"(a) : "l"(p));
    return a;
}
__device__ __forceinline__ void cpa16(uint32_t dst, const void* src) {
    asm volatile("cp.async.cg.shared.global [%0], [%1], 16;" :: "r"(dst), "l"(src) : "memory");
}
#define CP_COMMIT() asm volatile("cp.async.commit_group;" ::: "memory")
#define CP_WAIT(n)  asm volatile("cp.async.wait_group %0;" :: "n"(n) : "memory")

// =====================================================================
// K0a: transpose X [b][i][p] -> g_xr [b][p][i], tf32-rounded. occ 3.
// =====================================================================
#define XT_SMEM (128 * 129 * 4)
__global__ void __launch_bounds__(256, 3) k_xt(const float* __restrict__ X) {
    extern __shared__ float sm[];
    float* t = sm;
    const int tid = threadIdx.x;
    const int p0 = blockIdx.x * 128, i0 = blockIdx.y * 128, b = blockIdx.z;
    const float* src = X + ((size_t)(b * 512 + i0)) * 16384 + p0;
#pragma unroll
    for (int it = 0; it < 16; it++) {
        int idx = it * 256 + tid;
        int i = idx >> 5, p4 = (idx & 31) * 4;
        float4 v = *reinterpret_cast<const float4*>(src + (size_t)i * 16384 + p4);
        t[i * 129 + p4 + 0] = tf32f(v.x);
        t[i * 129 + p4 + 1] = tf32f(v.y);
        t[i * 129 + p4 + 2] = tf32f(v.z);
        t[i * 129 + p4 + 3] = tf32f(v.w);
    }
    __syncthreads();
    float* dst = g_xr + ((size_t)(b * 16384 + p0)) * 512 + i0;
#pragma unroll
    for (int it = 0; it < 16; it++) {
        int idx = it * 256 + tid;
        int p = idx >> 5, i4 = (idx & 31) * 4;
        float4 v;
        v.x = t[(i4 + 0) * 129 + p];
        v.y = t[(i4 + 1) * 129 + p];
        v.z = t[(i4 + 2) * 129 + p];
        v.w = t[(i4 + 3) * 129 + p];
        *reinterpret_cast<float4*>(dst + (size_t)p * 512 + i4) = v;
    }
}

// K0b: tf32-round a buffer (for W).
__global__ void k_round(const float* __restrict__ src, float* __restrict__ dst, int n4) {
    int i = blockIdx.x * blockDim.x + threadIdx.x;
    if (i < n4) {
        float4 v = reinterpret_cast<const float4*>(src)[i];
        reinterpret_cast<float4*>(dst)[i] = make_float4(tf32f(v.x), tf32f(v.y), tf32f(v.z), tf32f(v.w));
    }
}

// =====================================================================
// K1: QKV GEMM.  C[o, p] = sum_i Wr[o,i] * Xr[b][p,i] (+bias), p = s*128+l
// Both operands k-major in smem: [row][32 k] 128B rows, quad XOR swizzle.
// All fragment loads via ldmatrix.x4. 3-stage cp.async rotation.
// smem: A0/A1/A2 [0,49152), B0/B1/B2 [49152,98304). Cs [128][129] overlays.
// Outputs q,k,v written tf32-ROUNDED (post bias+scale).
// =====================================================================
#define K1_SMEM 98304

__global__ void __launch_bounds__(256, 2) k_qkv(const float* __restrict__ bias) {
    extern __shared__ float sm[];
    const uint32_t sb = smem_u32(sm);
    const int tid = threadIdx.x;
    const int warp = tid >> 5, lane = tid & 31;
    const int g = lane >> 2, qc = lane & 3;
    const int sub = lane >> 3, rr = lane & 7;       // ldmatrix lane decomposition
    const int wm = warp >> 2, wn = warp & 3;        // 2 x 4 warp grid
    const int o0 = blockIdx.x * 128;
    const int s = blockIdx.y;
    const int b = blockIdx.z;
    const float* Wt = g_wr + (size_t)o0 * 512;
    const float* Bt = g_xr + ((size_t)b * 16384 + (size_t)s * 128) * 512;

    float acc[4][4][4];
#pragma unroll
    for (int i = 0; i < 4; i++)
#pragma unroll
        for (int j = 0; j < 4; j++)
#pragma unroll
            for (int k = 0; k < 4; k++) acc[i][j][k] = 0.f;

    // stage chunk c: A [128 o][32 k] and B [128 p][32 k], both swizzled
    auto stage = [&](int c, int buf) {
        const float* wa = Wt + c * 32;
#pragma unroll
        for (int it = 0; it < 4; it++) {
            int idx = it * 256 + tid;          // 0..1023
            int r = idx >> 3;                  // row 0..127
            int kq = idx & 7;                  // k quad 0..7
            uint32_t dst = sb + (uint32_t)(buf * 16384 + r * 128 + ((kq ^ (r & 7)) << 4));
            cpa16(dst, wa + (size_t)r * 512 + kq * 4);
        }
        const float* xa = Bt + c * 32;
#pragma unroll
        for (int it = 0; it < 4; it++) {
            int idx = it * 256 + tid;
            int r = idx >> 3;
            int kq = idx & 7;
            uint32_t dst = sb + (uint32_t)(49152 + buf * 16384 + r * 128 + ((kq ^ (r & 7)) << 4));
            cpa16(dst, xa + (size_t)r * 512 + kq * 4);
        }
    };

    auto compute = [&](int buf) {
        const uint32_t Ab = sb + (uint32_t)(buf * 16384);
        const uint32_t Bb = sb + (uint32_t)(49152 + buf * 16384);
#pragma unroll
        for (int s8 = 0; s8 < 4; s8++) {
            uint32_t af[4][4], bf[2][4];
#pragma unroll
            for (int mt = 0; mt < 4; mt++) {
                int row = wm * 64 + mt * 16 + ((sub & 1) << 3) + rr;
                int q = 2 * s8 + (sub >> 1);
                ldsm4(af[mt], Ab + (uint32_t)(row * 128 + ((q ^ (row & 7)) << 4)));
            }
#pragma unroll
            for (int np = 0; np < 2; np++) {
                int n = wn * 32 + np * 16 + ((sub >> 1) << 3) + rr;
                int q = 2 * s8 + (sub & 1);
                ldsm4(bf[np], Bb + (uint32_t)(n * 128 + ((q ^ (n & 7)) << 4)));
            }
#pragma unroll
            for (int mt = 0; mt < 4; mt++)
#pragma unroll
                for (int nt = 0; nt < 4; nt++) {
                    const uint32_t bb[2] = { bf[nt >> 1][(nt & 1) * 2], bf[nt >> 1][(nt & 1) * 2 + 1] };
                    mma8(acc[mt][nt], af[mt], bb);
                }
        }
    };

    stage(0, 0);
    CP_COMMIT();
    stage(1, 1);
    CP_COMMIT();
    for (int c = 0; c < 16; c++) {
        if (c < 15) { CP_WAIT(1); } else { CP_WAIT(0); }
        __syncthreads();
        compute(c % 3);
        if (c + 2 < 16) {
            stage(c + 2, (c + 2) % 3);
            CP_COMMIT();
        }
    }
    __syncthreads();

    float* Cs = sm;   // [128][129]
#pragma unroll
    for (int mt = 0; mt < 4; mt++)
#pragma unroll
        for (int nt = 0; nt < 4; nt++) {
            int r = wm * 64 + mt * 16 + g;
            int n = wn * 32 + nt * 8 + 2 * qc;
            Cs[r * 129 + n] = acc[mt][nt][0];
            Cs[r * 129 + n + 1] = acc[mt][nt][1];
            Cs[(r + 8) * 129 + n] = acc[mt][nt][2];
            Cs[(r + 8) * 129 + n + 1] = acc[mt][nt][3];
        }
    __syncthreads();

    const int sel = o0 >> 9;                 // 0=q 1=k 2=v
    const int h0 = (o0 & 511) >> 6;
    float* dst = (sel == 0) ? g_q : ((sel == 1) ? g_k : g_v);
    const float scale = (sel == 0) ? 0.125f : 1.0f;
#pragma unroll
    for (int rep = 0; rep < 16; rep++) {
        int idx = rep * 256 + tid;
        int d4 = (idx & 15) * 4;
        int l = (idx >> 4) & 127;
        int hh = idx >> 11;
        int od = hh * 64 + d4;
        float4 v;
        v.x = tf32f((Cs[(od + 0) * 129 + l] + bias[o0 + od + 0]) * scale);
        v.y = tf32f((Cs[(od + 1) * 129 + l] + bias[o0 + od + 1]) * scale);
        v.z = tf32f((Cs[(od + 2) * 129 + l] + bias[o0 + od + 2]) * scale);
        v.w = tf32f((Cs[(od + 3) * 129 + l] + bias[o0 + od + 3]) * scale);
        size_t da = (((size_t)((b * 8 + h0 + hh) * 128 + s)) * 128 + l) * 64 + d4;
        *reinterpret_cast<float4*>(dst + da) = v;
    }
}

// =====================================================================
// Attention core: 128 x 128 x 64 per CTA, 8 warps, 2 CTA/SM.
// Q+K in cp.async group 0, V in group 1 (QK starts before V lands).
// QK: warp = 16 rows (shuffle softmax), frags via ldmatrix.
// PV: warp grid 4m x 2n; col writes STG direct from accumulators.
// smem: Qs[128][68] | Ks[128][68] | Vs[128][68]; Ps[128][132] overlays Qs+Ks.
// =====================================================================
#define ATTN_SMEM (3 * 128 * 68 * 4)   // 104,448 B
#define QS_OFF 0
#define KS_OFF (128 * 68 * 4)
#define VS_OFF (2 * 128 * 68 * 4)

// K2: column attention. Block = (l, h, b). Writes g_oc[b][h][s][l][d].
__global__ void __launch_bounds__(256, 2) k_colattn() {
    extern __shared__ float sm[];
    const uint32_t sb = smem_u32(sm);
    float* Vs = sm + 2 * 128 * 68;
    float* Ps = sm;                   // [128][132] overlay on Qs+Ks
    const int tid = threadIdx.x;
    const int warp = tid >> 5, lane = tid & 31;
    const int g = lane >> 2, qc = lane & 3;
    const int sub = lane >> 3, rr = lane & 7;
    const int l = blockIdx.x, h = blockIdx.y, b = blockIdx.z;
    const size_t base = (size_t)((b * 8 + h) * 128) * 8192;

    // group 0: Q + K; group 1: V
#pragma unroll
    for (int rep = 0; rep < 8; rep++) {
        int idx = rep * 256 + tid;
        int s = idx >> 4;
        int d4 = (idx & 15) * 4;
        size_t ga = base + (size_t)s * 8192 + (size_t)l * 64 + d4;
        uint32_t so = (uint32_t)(s * 68 + d4) * 4;
        cpa16(sb + QS_OFF + so, g_q + ga);
        cpa16(sb + KS_OFF + so, g_k + ga);
    }
    CP_COMMIT();
#pragma unroll
    for (int rep = 0; rep < 8; rep++) {
        int idx = rep * 256 + tid;
        int s = idx >> 4;
        int d4 = (idx & 15) * 4;
        size_t ga = base + (size_t)s * 8192 + (size_t)l * 64 + d4;
        cpa16(sb + VS_OFF + (uint32_t)(s * 68 + d4) * 4, g_v + ga);
    }
    CP_COMMIT();
    CP_WAIT(1);            // Q,K ready; V still in flight
    __syncthreads();

    // ---- QK: scores[s][t], warp owns rows 16w..16w+15 ----
    float sc[16][4];
#pragma unroll
    for (int nt = 0; nt < 16; nt++)
#pragma unroll
        for (int k = 0; k < 4; k++) sc[nt][k] = 0.f;
    const int row = warp * 16;
#pragma unroll
    for (int k0 = 0; k0 < 64; k0 += 8) {
        uint32_t a[4];
        {
            int rq = row + ((sub & 1) << 3) + rr;
            ldsm4(a, sb + QS_OFF + (uint32_t)(rq * 68 + k0 + ((sub >> 1) << 2)) * 4);
        }
#pragma unroll
        for (int np = 0; np < 8; np++) {
            uint32_t bf[4];
            int n = np * 16 + ((sub >> 1) << 3) + rr;
            ldsm4(bf, sb + KS_OFF + (uint32_t)(n * 68 + k0 + ((sub & 1) << 2)) * 4);
            const uint32_t b0[2] = { bf[0], bf[1] };
            const uint32_t b1[2] = { bf[2], bf[3] };
            mma8(sc[np * 2], a, b0);
            mma8(sc[np * 2 + 1], a, b1);
        }
    }
    // ---- softmax over t ----
    float m0 = -1e30f, m1 = -1e30f;
#pragma unroll
    for (int nt = 0; nt < 16; nt++) {
        m0 = fmaxf(m0, fmaxf(sc[nt][0], sc[nt][1]));
        m1 = fmaxf(m1, fmaxf(sc[nt][2], sc[nt][3]));
    }
    m0 = fmaxf(m0, __shfl_xor_sync(0xffffffffu, m0, 1));
    m0 = fmaxf(m0, __shfl_xor_sync(0xffffffffu, m0, 2));
    m1 = fmaxf(m1, __shfl_xor_sync(0xffffffffu, m1, 1));
    m1 = fmaxf(m1, __shfl_xor_sync(0xffffffffu, m1, 2));
    const float LOG2E = 1.4426950408889634f;
    float s0 = 0.f, s1 = 0.f;
#pragma unroll
    for (int nt = 0; nt < 16; nt++) {
        sc[nt][0] = exp2f((sc[nt][0] - m0) * LOG2E); s0 += sc[nt][0];
        sc[nt][1] = exp2f((sc[nt][1] - m0) * LOG2E); s0 += sc[nt][1];
        sc[nt][2] = exp2f((sc[nt][2] - m1) * LOG2E); s1 += sc[nt][2];
        sc[nt][3] = exp2f((sc[nt][3] - m1) * LOG2E); s1 += sc[nt][3];
    }
    s0 += __shfl_xor_sync(0xffffffffu, s0, 1);
    s0 += __shfl_xor_sync(0xffffffffu, s0, 2);
    s1 += __shfl_xor_sync(0xffffffffu, s1, 1);
    s1 += __shfl_xor_sync(0xffffffffu, s1, 2);
    const float inv0 = 1.0f / s0, inv1 = 1.0f / s1;

    __syncthreads();                         // Qs/Ks dead; Ps may overwrite
#pragma unroll
    for (int nt = 0; nt < 16; nt++) {
        int n = nt * 8 + 2 * qc;
        Ps[(row + g) * 132 + n] = tf32f(sc[nt][0] * inv0);
        Ps[(row + g) * 132 + n + 1] = tf32f(sc[nt][1] * inv0);
        Ps[(row + g + 8) * 132 + n] = tf32f(sc[nt][2] * inv1);
        Ps[(row + g + 8) * 132 + n + 1] = tf32f(sc[nt][3] * inv1);
    }
    CP_WAIT(0);                              // V landed long ago
    __syncthreads();

    // ---- PV: warp grid 4m x 2n ----
    const int wm2 = warp >> 1, wn2 = warp & 1;
    float oa[2][4][4];
#pragma unroll
    for (int mt = 0; mt < 2; mt++)
#pragma unroll
        for (int j = 0; j < 4; j++)
#pragma unroll
            for (int k = 0; k < 4; k++) oa[mt][j][k] = 0.f;
#pragma unroll
    for (int k0 = 0; k0 < 128; k0 += 8) {
        uint32_t a[2][4];
#pragma unroll
        for (int mt = 0; mt < 2; mt++) {
            int rp = wm2 * 32 + mt * 16 + ((sub & 1) << 3) + rr;
            ldsm4(a[mt], sb + QS_OFF + (uint32_t)(rp * 132 + k0 + ((sub >> 1) << 2)) * 4);
        }
#pragma unroll
        for (int j = 0; j < 4; j++) {
            uint32_t bb[2];
            int n = (wn2 * 4 + j) * 8 + g;
            bb[0] = fu(Vs[(k0 + qc) * 68 + n]);
            bb[1] = fu(Vs[(k0 + qc + 4) * 68 + n]);
#pragma unroll
            for (int mt = 0; mt < 2; mt++) mma8(oa[mt][j], a[mt], bb);
        }
    }
    // direct STG from accumulators: rows = s, cols = d
#pragma unroll
    for (int mt = 0; mt < 2; mt++)
#pragma unroll
        for (int j = 0; j < 4; j++) {
            int r2 = wm2 * 32 + mt * 16 + g;
            int n = (wn2 * 4 + j) * 8 + 2 * qc;
            float2 v0 = make_float2(oa[mt][j][0], oa[mt][j][1]);
            float2 v1 = make_float2(oa[mt][j][2], oa[mt][j][3]);
            *reinterpret_cast<float2*>(g_oc + base + (size_t)r2 * 8192 + (size_t)l * 64 + n) = v0;
            *reinterpret_cast<float2*>(g_oc + base + (size_t)(r2 + 8) * 8192 + (size_t)l * 64 + n) = v1;
        }
}

// K3: row attention + add col result + write final output [B,512,S,L].
__global__ void __launch_bounds__(256, 2) k_rowattn(float* __restrict__ out) {
    extern __shared__ float sm[];
    const uint32_t sb = smem_u32(sm);
    float* Vs = sm + 2 * 128 * 68;
    float* Ps = sm;                  // [128][132] overlay on Qs+Ks
    float* Os = sm;                  // [128][65] overlay
    const int tid = threadIdx.x;
    const int warp = tid >> 5, lane = tid & 31;
    const int g = lane >> 2, qc = lane & 3;
    const int sub = lane >> 3, rr = lane & 7;
    const int s = blockIdx.x, h = blockIdx.y, b = blockIdx.z;
    const size_t rbase = (size_t)((b * 8 + h) * 128) * 8192 + (size_t)s * 8192;

#pragma unroll
    for (int rep = 0; rep < 8; rep++) {
        int idx = rep * 256 + tid;
        int l = idx >> 4;
        int d4 = (idx & 15) * 4;
        size_t ga = rbase + (size_t)idx * 4;
        uint32_t so = (uint32_t)(l * 68 + d4) * 4;
        cpa16(sb + QS_OFF + so, g_q + ga);
        cpa16(sb + KS_OFF + so, g_k + ga);
    }
    CP_COMMIT();
#pragma unroll
    for (int rep = 0; rep < 8; rep++) {
        int idx = rep * 256 + tid;
        int l = idx >> 4;
        int d4 = (idx & 15) * 4;
        cpa16(sb + VS_OFF + (uint32_t)(l * 68 + d4) * 4, g_v + rbase + (size_t)idx * 4);
    }
    CP_COMMIT();
    CP_WAIT(1);
    __syncthreads();

    float sc[16][4];
#pragma unroll
    for (int nt = 0; nt < 16; nt++)
#pragma unroll
        for (int k = 0; k < 4; k++) sc[nt][k] = 0.f;
    const int row = warp * 16;
#pragma unroll
    for (int k0 = 0; k0 < 64; k0 += 8) {
        uint32_t a[4];
        {
            int rq = row + ((sub & 1) << 3) + rr;
            ldsm4(a, sb + QS_OFF + (uint32_t)(rq * 68 + k0 + ((sub >> 1) << 2)) * 4);
        }
#pragma unroll
        for (int np = 0; np < 8; np++) {
            uint32_t bf[4];
            int n = np * 16 + ((sub >> 1) << 3) + rr;
            ldsm4(bf, sb + KS_OFF + (uint32_t)(n * 68 + k0 + ((sub & 1) << 2)) * 4);
            const uint32_t b0[2] = { bf[0], bf[1] };
            const uint32_t b1[2] = { bf[2], bf[3] };
            mma8(sc[np * 2], a, b0);
            mma8(sc[np * 2 + 1], a, b1);
        }
    }
    float m0 = -1e30f, m1 = -1e30f;
#pragma unroll
    for (int nt = 0; nt < 16; nt++) {
        m0 = fmaxf(m0, fmaxf(sc[nt][0], sc[nt][1]));
        m1 = fmaxf(m1, fmaxf(sc[nt][2], sc[nt][3]));
    }
    m0 = fmaxf(m0, __shfl_xor_sync(0xffffffffu, m0, 1));
    m0 = fmaxf(m0, __shfl_xor_sync(0xffffffffu, m0, 2));
    m1 = fmaxf(m1, __shfl_xor_sync(0xffffffffu, m1, 1));
    m1 = fmaxf(m1, __shfl_xor_sync(0xffffffffu, m1, 2));
    const float LOG2E = 1.4426950408889634f;
    float s0 = 0.f, s1 = 0.f;
#pragma unroll
    for (int nt = 0; nt < 16; nt++) {
        sc[nt][0] = exp2f((sc[nt][0] - m0) * LOG2E); s0 += sc[nt][0];
        sc[nt][1] = exp2f((sc[nt][1] - m0) * LOG2E); s0 += sc[nt][1];
        sc[nt][2] = exp2f((sc[nt][2] - m1) * LOG2E); s1 += sc[nt][2];
        sc[nt][3] = exp2f((sc[nt][3] - m1) * LOG2E); s1 += sc[nt][3];
    }
    s0 += __shfl_xor_sync(0xffffffffu, s0, 1);
    s0 += __shfl_xor_sync(0xffffffffu, s0, 2);
    s1 += __shfl_xor_sync(0xffffffffu, s1, 1);
    s1 += __shfl_xor_sync(0xffffffffu, s1, 2);
    const float inv0 = 1.0f / s0, inv1 = 1.0f / s1;

    __syncthreads();
#pragma unroll
    for (int nt = 0; nt < 16; nt++) {
        int n = nt * 8 + 2 * qc;
        Ps[(row + g) * 132 + n] = tf32f(sc[nt][0] * inv0);
        Ps[(row + g) * 132 + n + 1] = tf32f(sc[nt][1] * inv0);
        Ps[(row + g + 8) * 132 + n] = tf32f(sc[nt][2] * inv1);
        Ps[(row + g + 8) * 132 + n + 1] = tf32f(sc[nt][3] * inv1);
    }
    CP_WAIT(0);
    __syncthreads();

    const int wm2 = warp >> 1, wn2 = warp & 1;
    float oa[2][4][4];
#pragma unroll
    for (int mt = 0; mt < 2; mt++)
#pragma unroll
        for (int j = 0; j < 4; j++)
#pragma unroll
            for (int k = 0; k < 4; k++) oa[mt][j][k] = 0.f;
#pragma unroll
    for (int k0 = 0; k0 < 128; k0 += 8) {
        uint32_t a[2][4];
#pragma unroll
        for (int mt = 0; mt < 2; mt++) {
            int rp = wm2 * 32 + mt * 16 + ((sub & 1) << 3) + rr;
            ldsm4(a[mt], sb + QS_OFF + (uint32_t)(rp * 132 + k0 + ((sub >> 1) << 2)) * 4);
        }
#pragma unroll
        for (int j = 0; j < 4; j++) {
            uint32_t bb[2];
            int n = (wn2 * 4 + j) * 8 + g;
            bb[0] = fu(Vs[(k0 + qc) * 68 + n]);
            bb[1] = fu(Vs[(k0 + qc + 4) * 68 + n]);
#pragma unroll
            for (int mt = 0; mt < 2; mt++) mma8(oa[mt][j], a[mt], bb);
        }
    }
    // fold col-attn result into accumulators (rows = l, cols = d)
#pragma unroll
    for (int mt = 0; mt < 2; mt++)
#pragma unroll
        for (int j = 0; j < 4; j++) {
            int lr = wm2 * 32 + mt * 16 + g;
            int n = (wn2 * 4 + j) * 8 + 2 * qc;
            float2 c0 = *reinterpret_cast<const float2*>(g_oc + rbase + (size_t)lr * 64 + n);
            float2 c1 = *reinterpret_cast<const float2*>(g_oc + rbase + (size_t)(lr + 8) * 64 + n);
            oa[mt][j][0] += c0.x;
            oa[mt][j][1] += c0.y;
            oa[mt][j][2] += c1.x;
            oa[mt][j][3] += c1.y;
        }
    __syncthreads();                 // all warps done reading Ps before Os overlay
#pragma unroll
    for (int mt = 0; mt < 2; mt++)
#pragma unroll
        for (int j = 0; j < 4; j++) {
            int r2 = wm2 * 32 + mt * 16 + g;
            int n = (wn2 * 4 + j) * 8 + 2 * qc;
            Os[r2 * 65 + n] = oa[mt][j][0];
            Os[r2 * 65 + n + 1] = oa[mt][j][1];
            Os[(r2 + 8) * 65 + n] = oa[mt][j][2];
            Os[(r2 + 8) * 65 + n + 1] = oa[mt][j][3];
        }
    __syncthreads();
    // transposed, fully coalesced final write: out[b][h*64+d][s][l]
#pragma unroll
    for (int rep = 0; rep < 8; rep++) {
        int idx = rep * 256 + tid;
        int d = idx >> 5;
        int l4 = (idx & 31) * 4;
        float4 v;
        v.x = Os[(l4 + 0) * 65 + d];
        v.y = Os[(l4 + 1) * 65 + d];
        v.z = Os[(l4 + 2) * 65 + d];
        v.w = Os[(l4 + 3) * 65 + d];
        size_t oaddr = (((size_t)(b * 512 + h * 64 + d)) * 128 + s) * 128 + l4;
        *reinterpret_cast<float4*>(out + oaddr) = v;
    }
}

extern "C" void kernel_launch(void* const* d_in, const int* in_sizes, int n_in,
                              void* d_out, int out_size) {
    const float* x = (const float*)d_in[0];
    const float* W = (const float*)d_in[1];
    const float* bias = (const float*)d_in[2];
    float* out = (float*)d_out;

    cudaFuncSetAttribute(k_xt, cudaFuncAttributeMaxDynamicSharedMemorySize, XT_SMEM);
    cudaFuncSetAttribute(k_qkv, cudaFuncAttributeMaxDynamicSharedMemorySize, K1_SMEM);
    cudaFuncSetAttribute(k_colattn, cudaFuncAttributeMaxDynamicSharedMemorySize, ATTN_SMEM);
    cudaFuncSetAttribute(k_rowattn, cudaFuncAttributeMaxDynamicSharedMemorySize, ATTN_SMEM);

    // X: transpose + round; W: round
    k_xt<<<dim3(128, 4, 2), 256, XT_SMEM>>>(x);
    {
        float* wr;  cudaGetSymbolAddress((void**)&wr, g_wr);
        int nw4 = 1536 * 512 / 4;            // 196,608
        k_round<<<(nw4 + 255) / 256, 256>>>(W, wr, nw4);
    }

    k_qkv<<<dim3(12, 128, 2), 256, K1_SMEM>>>(bias);
    k_colattn<<<dim3(128, 8, 2), 256, ATTN_SMEM>>>();
    k_rowattn<<<dim3(128, 8, 2), 256, ATTN_SMEM>>>(out);
}